// round 8
// baseline (speedup 1.0000x reference)
#include <cuda_runtime.h>
#include <cuda_bf16.h>
#include <cstdint>

#define BB 2
#define EM 512
#define NH 8
#define DH 64
#define TT 2048
#define EPS 1e-5f

// ---------------- scratch ----------------
__device__ __align__(256) __nv_bfloat16 g_WH[4][EM * EM];
__device__ __align__(256) __nv_bfloat16 g_WL[4][EM * EM];
__device__ __align__(256) __nv_bfloat16 g_XH[3][BB * TT * EM];
__device__ __align__(256) __nv_bfloat16 g_XL[3][BB * TT * EM];
__device__ __align__(256) float         g_Yp[BB * EM * TT];
__device__ __align__(256) __nv_bfloat16 g_Qb[BB * NH * TT * DH];
__device__ __align__(256) __nv_bfloat16 g_Kb[BB * NH * TT * DH];
__device__ __align__(256) __nv_bfloat16 g_Vb[BB * NH * DH * TT];
__device__ __align__(256) __nv_bfloat16 g_AoH[BB * TT * EM];
__device__ __align__(256) __nv_bfloat16 g_AoL[BB * TT * EM];
__device__ float g_Sv[BB * NH * DH];
__device__ float g_nv[BB];

// ---------------- helpers ----------------
__device__ __forceinline__ uint32_t smem_u32(const void* p) {
    uint32_t a;
    asm("{ .reg .u64 t; cvta.to.shared.u64 t, %1; cvt.u32.u64 %0, t; }" : "=r"(a) : "l"(p));
    return a;
}

__device__ __forceinline__ void ldm_x4(uint32_t* r, uint32_t a) {
    asm volatile("ldmatrix.sync.aligned.m8n8.x4.shared.b16 {%0,%1,%2,%3}, [%4];"
                 : "=r"(r[0]), "=r"(r[1]), "=r"(r[2]), "=r"(r[3]) : "r"(a));
}

__device__ __forceinline__ void mma16816(float* c, const uint32_t* a, const uint32_t* b) {
    asm volatile(
        "mma.sync.aligned.m16n8k16.row.col.f32.bf16.bf16.f32 "
        "{%0,%1,%2,%3}, {%4,%5,%6,%7}, {%8,%9}, {%0,%1,%2,%3};"
        : "+f"(c[0]), "+f"(c[1]), "+f"(c[2]), "+f"(c[3])
        : "r"(a[0]), "r"(a[1]), "r"(a[2]), "r"(a[3]), "r"(b[0]), "r"(b[1]));
}

// A-operand ldmatrix addr: 16x16 tile at (mo, ko), row-major, stride bytes
__device__ __forceinline__ uint32_t sA_addr(uint32_t base, int stride, int mo, int ko, int lane) {
    int j = lane >> 3, r = lane & 7;
    return base + (uint32_t)((mo + ((j & 1) << 3) + r) * stride + (ko + ((j >> 1) << 3)) * 2);
}
// B-operand (two n-frags) ldmatrix addr: rows = n (K-major storage)
__device__ __forceinline__ uint32_t sB_addr(uint32_t base, int stride, int no, int ko, int lane) {
    int j = lane >> 3, r = lane & 7;
    return base + (uint32_t)((no + ((j >> 1) << 3) + r) * stride + (ko + ((j & 1) << 3)) * 2);
}

__device__ __forceinline__ float expm1p(float s) {
    float p = 1.f / 720.f;
    p = fmaf(p, s, 1.f / 120.f);
    p = fmaf(p, s, 1.f / 24.f);
    p = fmaf(p, s, 1.f / 6.f);
    p = fmaf(p, s, 0.5f);
    p = fmaf(p, s, 1.f);
    return p * s;
}

// ---------------- prep kernels ----------------
// all 4 weights in one launch: blockIdx.y selects matrix
__global__ void __launch_bounds__(128) prep_w4(const float* __restrict__ W0,
                                               const float* __restrict__ W1,
                                               const float* __restrict__ W2,
                                               const float* __restrict__ W3) {
    __shared__ float red[8];
    const float* Ws[4] = {W0, W1, W2, W3};
    int i = blockIdx.y, row = blockIdx.x, tid = threadIdx.x;
    const float* wr = Ws[i] + (size_t)row * EM;
    __nv_bfloat16* WH = g_WH[i];
    __nv_bfloat16* WL = g_WL[i];
    float s = 0.f, s2 = 0.f;
    for (int c = tid; c < EM; c += 128) { float v = wr[c]; s += v; s2 += v * v; }
    for (int o = 16; o; o >>= 1) { s += __shfl_xor_sync(~0u, s, o); s2 += __shfl_xor_sync(~0u, s2, o); }
    if ((tid & 31) == 0) { red[tid >> 5] = s; red[4 + (tid >> 5)] = s2; }
    __syncthreads();
    s = red[0] + red[1] + red[2] + red[3];
    s2 = red[4] + red[5] + red[6] + red[7];
    float mu = s * (1.f / EM), var = s2 * (1.f / EM) - mu * mu, r = rsqrtf(var + EPS);
    for (int c = tid; c < EM; c += 128) {
        float wn = (wr[c] - mu) * r;
        __nv_bfloat16 h = __float2bfloat16(wn);
        WH[(size_t)row * EM + c] = h;
        WL[(size_t)row * EM + c] = __float2bfloat16(wn - __bfloat162float(h));
    }
}

// all 3 inputs in one launch: blockIdx.z = which*BB + b
__global__ void prep_x3(const float* __restrict__ x0, const float* __restrict__ x1,
                        const float* __restrict__ x2,
                        const int* __restrict__ m0, const int* __restrict__ m1,
                        const int* __restrict__ m2) {
    __shared__ float s[32][33];
    const float* Xs[3] = {x0, x1, x2};
    const int* Ms[3] = {m0, m1, m2};
    int which = blockIdx.z >> 1, b = blockIdx.z & 1;
    const float* X = Xs[which];
    const int* mask = Ms[which];
    __nv_bfloat16* XH = g_XH[which];
    __nv_bfloat16* XL = g_XL[which];
    int t0 = blockIdx.x * 32, i0 = blockIdx.y * 32;
    int tx = threadIdx.x, ty = threadIdx.y;
#pragma unroll
    for (int rr = 0; rr < 4; rr++)
        s[ty + 8 * rr][tx] = X[((size_t)b * EM + i0 + ty + 8 * rr) * TT + t0 + tx];
    __syncthreads();
#pragma unroll
    for (int rr = 0; rr < 4; rr++) {
        int tl = ty + 8 * rr, t = t0 + tl;
        float x = s[tx][tl] * (float)mask[b * TT + t];
        __nv_bfloat16 h = __float2bfloat16(x);
        size_t o = ((size_t)b * TT + t) * EM + i0 + tx;
        XH[o] = h;
        XL[o] = __float2bfloat16(x - __bfloat162float(h));
    }
}

// zero g_Sv + count valid keys, one launch, grid = BB
__global__ void init_aux(const int* __restrict__ km) {
    __shared__ float red[8];
    int b = blockIdx.x, tid = threadIdx.x;
    for (int i = tid; i < NH * DH; i += 256) g_Sv[b * NH * DH + i] = 0.f;
    float c = 0.f;
    for (int t = tid; t < TT; t += 256) c += (float)km[b * TT + t];
    for (int o = 16; o; o >>= 1) c += __shfl_xor_sync(~0u, c, o);
    if ((tid & 31) == 0) red[tid >> 5] = c;
    __syncthreads();
    if (tid == 0) {
        float tt = 0.f;
        for (int w = 0; w < 8; w++) tt += red[w];
        g_nv[b] = tt;
    }
}

// ---------------- projection GEMM (mma.sync bf16 split-3) ----------------
__global__ void __launch_bounds__(256) proj_wmma(
    const __nv_bfloat16* __restrict__ AH, const __nv_bfloat16* __restrict__ AL,
    const __nv_bfloat16* __restrict__ BH, const __nv_bfloat16* __restrict__ BL,
    const float* __restrict__ bias, float* __restrict__ Y)
{
    extern __shared__ __align__(16) char smc[];
    __nv_bfloat16* sAh = (__nv_bfloat16*)smc;      // [128][72]
    __nv_bfloat16* sAl = sAh + 128 * 72;
    __nv_bfloat16* sBh = sAl + 128 * 72;
    __nv_bfloat16* sBl = sBh + 128 * 72;
    uint32_t bAh = smem_u32(sAh), bAl = smem_u32(sAl);
    uint32_t bBh = smem_u32(sBh), bBl = smem_u32(sBl);
    int tid = threadIdx.x, lane = tid & 31, wid = tid >> 5;
    int wm = wid >> 2, wn = wid & 3;
    int t0 = blockIdx.x * 128, m0 = blockIdx.y * 128, b = blockIdx.z;
    const __nv_bfloat16* gAh = AH + (size_t)m0 * EM;
    const __nv_bfloat16* gAl = AL + (size_t)m0 * EM;
    const __nv_bfloat16* gBh = BH + ((size_t)b * TT + t0) * EM;
    const __nv_bfloat16* gBl = BL + ((size_t)b * TT + t0) * EM;

    float acc[4][4][4] = {};

    for (int kc = 0; kc < 8; kc++) {
        int k0 = kc * 64;
        __syncthreads();
        for (int idx = tid; idx < 1024; idx += 256) {
            int r = idx >> 3, j = idx & 7;
            *(uint4*)(sAh + r * 72 + j * 8) = *(const uint4*)(gAh + (size_t)r * EM + k0 + j * 8);
            *(uint4*)(sAl + r * 72 + j * 8) = *(const uint4*)(gAl + (size_t)r * EM + k0 + j * 8);
            *(uint4*)(sBh + r * 72 + j * 8) = *(const uint4*)(gBh + (size_t)r * EM + k0 + j * 8);
            *(uint4*)(sBl + r * 72 + j * 8) = *(const uint4*)(gBl + (size_t)r * EM + k0 + j * 8);
        }
        __syncthreads();
#pragma unroll
        for (int ks = 0; ks < 4; ks++) {
            uint32_t ah[4][4], al[4][4], bh[2][4], bl[2][4];
#pragma unroll
            for (int mf = 0; mf < 4; mf++) {
                ldm_x4(ah[mf], sA_addr(bAh, 144, wm * 64 + mf * 16, ks * 16, lane));
                ldm_x4(al[mf], sA_addr(bAl, 144, wm * 64 + mf * 16, ks * 16, lane));
            }
#pragma unroll
            for (int np = 0; np < 2; np++) {
                ldm_x4(bh[np], sB_addr(bBh, 144, wn * 32 + np * 16, ks * 16, lane));
                ldm_x4(bl[np], sB_addr(bBl, 144, wn * 32 + np * 16, ks * 16, lane));
            }
#pragma unroll
            for (int mf = 0; mf < 4; mf++)
#pragma unroll
                for (int nf = 0; nf < 4; nf++) {
                    const uint32_t* ph = &bh[nf >> 1][(nf & 1) * 2];
                    const uint32_t* pl = &bl[nf >> 1][(nf & 1) * 2];
                    mma16816(acc[mf][nf], ah[mf], ph);
                    mma16816(acc[mf][nf], ah[mf], pl);
                    mma16816(acc[mf][nf], al[mf], ph);
                }
        }
    }
#pragma unroll
    for (int mf = 0; mf < 4; mf++)
#pragma unroll
        for (int rr = 0; rr < 2; rr++) {
            int m = m0 + wm * 64 + mf * 16 + (lane >> 2) + rr * 8;
            float bi = bias[m];
            float* yo = Y + ((size_t)b * EM + m) * TT + t0 + wn * 32;
#pragma unroll
            for (int nf = 0; nf < 4; nf++) {
                float2 v = make_float2(acc[mf][nf][rr * 2] + bi, acc[mf][nf][rr * 2 + 1] + bi);
                *(float2*)(yo + nf * 8 + 2 * (lane & 3)) = v;
            }
        }
}

// ---------------- per-head LN + emit bf16 ----------------
__global__ void __launch_bounds__(256) ln_emit(
    const float* __restrict__ Y, const float* __restrict__ g, const float* __restrict__ be,
    __nv_bfloat16* __restrict__ oTD, __nv_bfloat16* __restrict__ oDT,
    const int* __restrict__ km, int mode) {
    __shared__ float sacc[64];
    int t = blockIdx.x * 256 + threadIdx.x, h = blockIdx.y, b = blockIdx.z;
    const float* base = Y + ((size_t)b * EM + h * 64) * TT + t;
    float v[64];
    float s = 0.f, s2 = 0.f;
#pragma unroll
    for (int d = 0; d < 64; d++) { v[d] = base[(size_t)d * TT]; s += v[d]; s2 += v[d] * v[d]; }
    float mu = s * (1.f / 64), var = s2 * (1.f / 64) - mu * mu, rs = rsqrtf(var + EPS);
#pragma unroll
    for (int d = 0; d < 64; d++) v[d] = (v[d] - mu) * rs * g[d] + be[d];
    if (mode == 0) {
        __nv_bfloat16* o = oTD + (((size_t)b * NH + h) * TT + t) * 64;
#pragma unroll
        for (int dd = 0; dd < 64; dd += 8) {
            uint32_t pk[4];
#pragma unroll
            for (int e = 0; e < 4; e++) {
                __nv_bfloat162 p = __floats2bfloat162_rn(v[dd + 2 * e], v[dd + 2 * e + 1]);
                pk[e] = *(uint32_t*)&p;
            }
            *(uint4*)(o + dd) = *(uint4*)pk;
        }
    } else {
        __nv_bfloat16* o = oDT + ((size_t)b * NH + h) * (size_t)(64 * TT) + t;
#pragma unroll
        for (int d = 0; d < 64; d++) o[(size_t)d * TT] = __float2bfloat16(v[d]);
        if (threadIdx.x < 64) sacc[threadIdx.x] = 0.f;
        __syncthreads();
        float w = (float)km[b * TT + t];
#pragma unroll
        for (int d = 0; d < 64; d++) {
            float x = v[d] * w;
            for (int off = 16; off; off >>= 1) x += __shfl_xor_sync(~0u, x, off);
            if ((threadIdx.x & 31) == 0) atomicAdd(&sacc[d], x);
        }
        __syncthreads();
        if (threadIdx.x < 64) atomicAdd(&g_Sv[((size_t)b * NH + h) * 64 + threadIdx.x], sacc[threadIdx.x]);
    }
}

// ---------------- fused attention (mma.sync, register-resident U) ----------------
// 8 warps; warp w owns q rows [w*16, w*16+16) x ALL 128 k columns per chunk.
// S accumulators convert in-register to U A-fragments (accum layout == A-frag layout).
__global__ void __launch_bounds__(256) attn_wmma(const int* __restrict__ qmask,
                                                 const int* __restrict__ kmask)
{
    extern __shared__ __align__(16) char smc[];
    __nv_bfloat16* sQ = (__nv_bfloat16*)smc;       // [128][72]
    __nv_bfloat16* sK = sQ + 128 * 72;             // [128][72]
    __nv_bfloat16* sV = sK + 128 * 72;             // [64][136]
    float* kms = (float*)(sV + 64 * 136);          // [128]
    uint32_t aQ = smem_u32(sQ), aK = smem_u32(sK), aV = smem_u32(sV);
    int tid = threadIdx.x, lane = tid & 31, wid = tid >> 5;
    int g = lane >> 2, tig = lane & 3;
    int q0 = blockIdx.x * 128;
    int b = blockIdx.y >> 3, h = blockIdx.y & 7;
    size_t hb = (size_t)(b * NH + h);
    const __nv_bfloat16* gQ = g_Qb + (hb * TT + q0) * 64;
    const __nv_bfloat16* gK = g_Kb + hb * TT * 64;
    const __nv_bfloat16* gV = g_Vb + hb * (size_t)(64 * TT);

    for (int idx = tid; idx < 1024; idx += 256) {
        int r = idx >> 3, j = idx & 7;
        *(uint4*)(sQ + r * 72 + j * 8) = *(const uint4*)(gQ + (size_t)r * 64 + j * 8);
    }

    float oc[8][4] = {};
    float rs0 = 0.f, rs1 = 0.f;
    const float inv181 = 1.f / 181.f;

    for (int kc = 0; kc < 16; kc++) {
        int k0 = kc * 128;
        __syncthreads();
        for (int idx = tid; idx < 1024; idx += 256) {
            int r = idx >> 3, j = idx & 7;
            *(uint4*)(sK + r * 72 + j * 8) = *(const uint4*)(gK + (size_t)(k0 + r) * 64 + j * 8);
        }
        for (int idx = tid; idx < 1024; idx += 256) {
            int r = idx >> 4, j = idx & 15;
            *(uint4*)(sV + r * 136 + j * 8) = *(const uint4*)(gV + (size_t)r * TT + k0 + j * 8);
        }
        if (tid < 128) kms[tid] = (float)kmask[b * TT + k0 + tid];
        __syncthreads();

        // S = Q @ K^T : 16q x 128k per warp
        float sc[16][4] = {};
#pragma unroll
        for (int ks = 0; ks < 4; ks++) {
            uint32_t aq[4];
            ldm_x4(aq, sA_addr(aQ, 144, wid * 16, ks * 16, lane));
#pragma unroll
            for (int nb = 0; nb < 8; nb++) {
                uint32_t bk[4];
                ldm_x4(bk, sB_addr(aK, 144, nb * 16, ks * 16, lane));
                mma16816(sc[2 * nb], aq, &bk[0]);
                mma16816(sc[2 * nb + 1], aq, &bk[2]);
            }
        }

        // convert S -> U A-fragments in registers (accum layout == A-frag layout)
        uint32_t ua[8][4];
#pragma unroll
        for (int nf = 0; nf < 16; nf++) {
            int c0 = nf * 8 + 2 * tig;
            float k0f = kms[c0], k1f = kms[c0 + 1];
            float u0 = expm1p(sc[nf][0] * inv181) * k0f;
            float u1 = expm1p(sc[nf][1] * inv181) * k1f;
            float u2 = expm1p(sc[nf][2] * inv181) * k0f;
            float u3 = expm1p(sc[nf][3] * inv181) * k1f;
            rs0 += u0 + u1;
            rs1 += u2 + u3;
            __nv_bfloat162 p01 = __floats2bfloat162_rn(u0, u1);
            __nv_bfloat162 p23 = __floats2bfloat162_rn(u2, u3);
            int kk = nf >> 1, hi = (nf & 1) * 2;
            ua[kk][hi] = *(uint32_t*)&p01;
            ua[kk][hi + 1] = *(uint32_t*)&p23;
        }

        // O += U @ V^T : 16q x 64d, contraction over this chunk's 128 k
#pragma unroll
        for (int kk = 0; kk < 8; kk++) {
#pragma unroll
            for (int db = 0; db < 4; db++) {
                uint32_t bv[4];
                ldm_x4(bv, sB_addr(aV, 272, db * 16, kk * 16, lane));
                mma16816(oc[2 * db], ua[kk], &bv[0]);
                mma16816(oc[2 * db + 1], ua[kk], &bv[2]);
            }
        }
    }

    // rowsums: reduce across the 4 lanes of each quad (warp owns full k)
    rs0 += __shfl_xor_sync(~0u, rs0, 1);
    rs0 += __shfl_xor_sync(~0u, rs0, 2);
    rs1 += __shfl_xor_sync(~0u, rs1, 1);
    rs1 += __shfl_xor_sync(~0u, rs1, 2);

    float nv = g_nv[b];
    const float* sv = g_Sv + hb * 64;
#pragma unroll
    for (int rr = 0; rr < 2; rr++) {
        int row = wid * 16 + g + rr * 8;
        int q = q0 + row;
        float l = nv + (rr ? rs1 : rs0);
        float inv = (qmask[b * TT + q] != 0) ? (1.f / l) : 0.f;
        __nv_bfloat16* oH = g_AoH + ((size_t)b * TT + q) * EM + h * 64;
        __nv_bfloat16* oL = g_AoL + ((size_t)b * TT + q) * EM + h * 64;
#pragma unroll
        for (int df = 0; df < 8; df++) {
            int d0 = df * 8 + 2 * tig;
            float x0 = (oc[df][rr * 2] + sv[d0]) * inv;
            float x1 = (oc[df][rr * 2 + 1] + sv[d0 + 1]) * inv;
            __nv_bfloat16 h0 = __float2bfloat16(x0), h1 = __float2bfloat16(x1);
            __nv_bfloat162 ph = __halves2bfloat162(h0, h1);
            __nv_bfloat162 pl = __floats2bfloat162_rn(x0 - __bfloat162float(h0),
                                                      x1 - __bfloat162float(h1));
            *(uint32_t*)(oH + d0) = *(uint32_t*)&ph;
            *(uint32_t*)(oL + d0) = *(uint32_t*)&pl;
        }
    }
}

// ---------------- launch ----------------
extern "C" void kernel_launch(void* const* d_in, const int* in_sizes, int n_in,
                              void* d_out, int out_size) {
    const float* q  = (const float*)d_in[0];
    const float* k  = (const float*)d_in[1];
    const float* v  = (const float*)d_in[2];
    const int* qm   = (const int*)d_in[3];
    const int* km   = (const int*)d_in[4];
    const int* vm   = (const int*)d_in[5];
    const float* W[4]  = {(const float*)d_in[6], (const float*)d_in[8], (const float*)d_in[10], (const float*)d_in[12]};
    const float* bi[4] = {(const float*)d_in[7], (const float*)d_in[9], (const float*)d_in[11], (const float*)d_in[13]};
    const float* lng[3] = {(const float*)d_in[14], (const float*)d_in[16], (const float*)d_in[18]};
    const float* lnb[3] = {(const float*)d_in[15], (const float*)d_in[17], (const float*)d_in[19]};
    float* out = (float*)d_out;

    void *pWH, *pWL, *pXH, *pXL, *pY, *pQ, *pK, *pV, *pAH, *pAL;
    cudaGetSymbolAddress(&pWH, g_WH); cudaGetSymbolAddress(&pWL, g_WL);
    cudaGetSymbolAddress(&pXH, g_XH); cudaGetSymbolAddress(&pXL, g_XL);
    cudaGetSymbolAddress(&pY, g_Yp);
    cudaGetSymbolAddress(&pQ, g_Qb); cudaGetSymbolAddress(&pK, g_Kb); cudaGetSymbolAddress(&pV, g_Vb);
    cudaGetSymbolAddress(&pAH, g_AoH); cudaGetSymbolAddress(&pAL, g_AoL);
    __nv_bfloat16* WH = (__nv_bfloat16*)pWH;
    __nv_bfloat16* WL = (__nv_bfloat16*)pWL;
    __nv_bfloat16* XH = (__nv_bfloat16*)pXH;
    __nv_bfloat16* XL = (__nv_bfloat16*)pXL;
    float* Yp = (float*)pY;

    const int PROJ_SMEM = 4 * 128 * 72 * 2;                              // 73728
    const int ATTN_SMEM = (2 * 128 * 72 + 64 * 136) * 2 + 128 * 4;       // 54784
    cudaFuncSetAttribute(proj_wmma, cudaFuncAttributeMaxDynamicSharedMemorySize, PROJ_SMEM);
    cudaFuncSetAttribute(attn_wmma, cudaFuncAttributeMaxDynamicSharedMemorySize, ATTN_SMEM);

    prep_w4<<<dim3(EM, 4), 128>>>(W[0], W[1], W[2], W[3]);
    prep_x3<<<dim3(TT / 32, EM / 32, 3 * BB), dim3(32, 8)>>>(q, k, v, qm, km, vm);
    init_aux<<<BB, 256>>>(km);

    dim3 gp(TT / 128, EM / 128, BB);
    dim3 gl(TT / 256, NH, BB);
    for (int i = 0; i < 3; i++) {
        proj_wmma<<<gp, 256, PROJ_SMEM>>>(WH + (size_t)i * EM * EM, WL + (size_t)i * EM * EM,
                                          XH + (size_t)i * BB * TT * EM, XL + (size_t)i * BB * TT * EM,
                                          bi[i], Yp);
        if (i == 0)      ln_emit<<<gl, 256>>>(Yp, lng[0], lnb[0], (__nv_bfloat16*)pQ, nullptr, km, 0);
        else if (i == 1) ln_emit<<<gl, 256>>>(Yp, lng[1], lnb[1], (__nv_bfloat16*)pK, nullptr, km, 0);
        else             ln_emit<<<gl, 256>>>(Yp, lng[2], lnb[2], nullptr, (__nv_bfloat16*)pV, km, 1);
    }

    attn_wmma<<<dim3(TT / 128, BB * NH), 256, ATTN_SMEM>>>(qm, km);

    proj_wmma<<<gp, 256, PROJ_SMEM>>>(WH + (size_t)3 * EM * EM, WL + (size_t)3 * EM * EM,
                                      (__nv_bfloat16*)pAH, (__nv_bfloat16*)pAL, bi[3], out);
}

// round 9
// speedup vs baseline: 1.1689x; 1.1689x over previous
#include <cuda_runtime.h>
#include <cuda_bf16.h>
#include <cstdint>

#define BB 2
#define EM 512
#define NH 8
#define DH 64
#define TT 2048
#define EPS 1e-5f

// ---------------- scratch ----------------
__device__ __align__(256) __nv_bfloat16 g_WH[4][EM * EM];
__device__ __align__(256) __nv_bfloat16 g_WL[4][EM * EM];
__device__ __align__(256) __nv_bfloat16 g_XH[3][BB * TT * EM];
__device__ __align__(256) __nv_bfloat16 g_XL[3][BB * TT * EM];
__device__ __align__(256) float         g_Yp[BB * EM * TT];
__device__ __align__(256) __nv_bfloat16 g_Qb[BB * NH * TT * DH];
__device__ __align__(256) __nv_bfloat16 g_Kb[BB * NH * TT * DH];
__device__ __align__(256) __nv_bfloat16 g_Vb[BB * NH * DH * TT];
__device__ __align__(256) __nv_bfloat16 g_AoH[BB * TT * EM];
__device__ __align__(256) __nv_bfloat16 g_AoL[BB * TT * EM];
__device__ float g_Sv[BB * NH * DH];
__device__ float g_nv[BB];

// ---------------- helpers ----------------
__device__ __forceinline__ uint32_t smem_u32(const void* p) {
    uint32_t a;
    asm("{ .reg .u64 t; cvta.to.shared.u64 t, %1; cvt.u32.u64 %0, t; }" : "=r"(a) : "l"(p));
    return a;
}

__device__ __forceinline__ void ldm_x4(uint32_t* r, uint32_t a) {
    asm volatile("ldmatrix.sync.aligned.m8n8.x4.shared.b16 {%0,%1,%2,%3}, [%4];"
                 : "=r"(r[0]), "=r"(r[1]), "=r"(r[2]), "=r"(r[3]) : "r"(a));
}

__device__ __forceinline__ void mma16816(float* c, const uint32_t* a, const uint32_t* b) {
    asm volatile(
        "mma.sync.aligned.m16n8k16.row.col.f32.bf16.bf16.f32 "
        "{%0,%1,%2,%3}, {%4,%5,%6,%7}, {%8,%9}, {%0,%1,%2,%3};"
        : "+f"(c[0]), "+f"(c[1]), "+f"(c[2]), "+f"(c[3])
        : "r"(a[0]), "r"(a[1]), "r"(a[2]), "r"(a[3]), "r"(b[0]), "r"(b[1]));
}

// A-operand ldmatrix addr: 16x16 tile at (mo, ko), row-major, stride bytes
__device__ __forceinline__ uint32_t sA_addr(uint32_t base, int stride, int mo, int ko, int lane) {
    int j = lane >> 3, r = lane & 7;
    return base + (uint32_t)((mo + ((j & 1) << 3) + r) * stride + (ko + ((j >> 1) << 3)) * 2);
}
// B-operand (two n-frags) ldmatrix addr: rows = n (K-major storage)
__device__ __forceinline__ uint32_t sB_addr(uint32_t base, int stride, int no, int ko, int lane) {
    int j = lane >> 3, r = lane & 7;
    return base + (uint32_t)((no + ((j >> 1) << 3) + r) * stride + (ko + ((j & 1) << 3)) * 2);
}

__device__ __forceinline__ float expm1p(float s) {
    float p = 1.f / 720.f;
    p = fmaf(p, s, 1.f / 120.f);
    p = fmaf(p, s, 1.f / 24.f);
    p = fmaf(p, s, 1.f / 6.f);
    p = fmaf(p, s, 0.5f);
    p = fmaf(p, s, 1.f);
    return p * s;
}

// ---------------- prep kernels ----------------
__global__ void __launch_bounds__(128) prep_w4(const float* __restrict__ W0,
                                               const float* __restrict__ W1,
                                               const float* __restrict__ W2,
                                               const float* __restrict__ W3) {
    __shared__ float red[8];
    const float* Ws[4] = {W0, W1, W2, W3};
    int i = blockIdx.y, row = blockIdx.x, tid = threadIdx.x;
    const float* wr = Ws[i] + (size_t)row * EM;
    __nv_bfloat16* WH = g_WH[i];
    __nv_bfloat16* WL = g_WL[i];
    float s = 0.f, s2 = 0.f;
    for (int c = tid; c < EM; c += 128) { float v = wr[c]; s += v; s2 += v * v; }
    for (int o = 16; o; o >>= 1) { s += __shfl_xor_sync(~0u, s, o); s2 += __shfl_xor_sync(~0u, s2, o); }
    if ((tid & 31) == 0) { red[tid >> 5] = s; red[4 + (tid >> 5)] = s2; }
    __syncthreads();
    s = red[0] + red[1] + red[2] + red[3];
    s2 = red[4] + red[5] + red[6] + red[7];
    float mu = s * (1.f / EM), var = s2 * (1.f / EM) - mu * mu, r = rsqrtf(var + EPS);
    for (int c = tid; c < EM; c += 128) {
        float wn = (wr[c] - mu) * r;
        __nv_bfloat16 h = __float2bfloat16(wn);
        WH[(size_t)row * EM + c] = h;
        WL[(size_t)row * EM + c] = __float2bfloat16(wn - __bfloat162float(h));
    }
}

__global__ void prep_x3(const float* __restrict__ x0, const float* __restrict__ x1,
                        const float* __restrict__ x2,
                        const int* __restrict__ m0, const int* __restrict__ m1,
                        const int* __restrict__ m2) {
    __shared__ float s[32][33];
    const float* Xs[3] = {x0, x1, x2};
    const int* Ms[3] = {m0, m1, m2};
    int which = blockIdx.z >> 1, b = blockIdx.z & 1;
    const float* X = Xs[which];
    const int* mask = Ms[which];
    __nv_bfloat16* XH = g_XH[which];
    __nv_bfloat16* XL = g_XL[which];
    int t0 = blockIdx.x * 32, i0 = blockIdx.y * 32;
    int tx = threadIdx.x, ty = threadIdx.y;
#pragma unroll
    for (int rr = 0; rr < 4; rr++)
        s[ty + 8 * rr][tx] = X[((size_t)b * EM + i0 + ty + 8 * rr) * TT + t0 + tx];
    __syncthreads();
#pragma unroll
    for (int rr = 0; rr < 4; rr++) {
        int tl = ty + 8 * rr, t = t0 + tl;
        float x = s[tx][tl] * (float)mask[b * TT + t];
        __nv_bfloat16 h = __float2bfloat16(x);
        size_t o = ((size_t)b * TT + t) * EM + i0 + tx;
        XH[o] = h;
        XL[o] = __float2bfloat16(x - __bfloat162float(h));
    }
}

__global__ void init_aux(const int* __restrict__ km) {
    __shared__ float red[8];
    int b = blockIdx.x, tid = threadIdx.x;
    for (int i = tid; i < NH * DH; i += 256) g_Sv[b * NH * DH + i] = 0.f;
    float c = 0.f;
    for (int t = tid; t < TT; t += 256) c += (float)km[b * TT + t];
    for (int o = 16; o; o >>= 1) c += __shfl_xor_sync(~0u, c, o);
    if ((tid & 31) == 0) red[tid >> 5] = c;
    __syncthreads();
    if (tid == 0) {
        float tt = 0.f;
        for (int w = 0; w < 8; w++) tt += red[w];
        g_nv[b] = tt;
    }
}

// ---------------- projection GEMM (mma.sync bf16 split-3) ----------------
// block tile 128m x 64t, 8 warps = 4m x 2t (warp tile 32x32); grid 256 blocks -> 2 CTAs/SM
__global__ void __launch_bounds__(256, 2) proj_wmma(
    const __nv_bfloat16* __restrict__ AH, const __nv_bfloat16* __restrict__ AL,
    const __nv_bfloat16* __restrict__ BH, const __nv_bfloat16* __restrict__ BL,
    const float* __restrict__ bias, float* __restrict__ Y)
{
    extern __shared__ __align__(16) char smc[];
    __nv_bfloat16* sAh = (__nv_bfloat16*)smc;      // [128][72]
    __nv_bfloat16* sAl = sAh + 128 * 72;
    __nv_bfloat16* sBh = sAl + 128 * 72;           // [64][72]
    __nv_bfloat16* sBl = sBh + 64 * 72;
    uint32_t bAh = smem_u32(sAh), bAl = smem_u32(sAl);
    uint32_t bBh = smem_u32(sBh), bBl = smem_u32(sBl);
    int tid = threadIdx.x, lane = tid & 31, wid = tid >> 5;
    int wm = wid >> 1, wn = wid & 1;
    int t0 = blockIdx.x * 64, m0 = blockIdx.y * 128, b = blockIdx.z;
    const __nv_bfloat16* gAh = AH + (size_t)m0 * EM;
    const __nv_bfloat16* gAl = AL + (size_t)m0 * EM;
    const __nv_bfloat16* gBh = BH + ((size_t)b * TT + t0) * EM;
    const __nv_bfloat16* gBl = BL + ((size_t)b * TT + t0) * EM;

    float acc[2][4][4] = {};

    for (int kc = 0; kc < 8; kc++) {
        int k0 = kc * 64;
        __syncthreads();
        for (int idx = tid; idx < 1024; idx += 256) {
            int r = idx >> 3, j = idx & 7;
            *(uint4*)(sAh + r * 72 + j * 8) = *(const uint4*)(gAh + (size_t)r * EM + k0 + j * 8);
            *(uint4*)(sAl + r * 72 + j * 8) = *(const uint4*)(gAl + (size_t)r * EM + k0 + j * 8);
        }
        for (int idx = tid; idx < 512; idx += 256) {
            int r = idx >> 3, j = idx & 7;
            *(uint4*)(sBh + r * 72 + j * 8) = *(const uint4*)(gBh + (size_t)r * EM + k0 + j * 8);
            *(uint4*)(sBl + r * 72 + j * 8) = *(const uint4*)(gBl + (size_t)r * EM + k0 + j * 8);
        }
        __syncthreads();
#pragma unroll
        for (int ks = 0; ks < 4; ks++) {
            uint32_t ah[2][4], al[2][4], bh[2][4], bl[2][4];
#pragma unroll
            for (int mf = 0; mf < 2; mf++) {
                ldm_x4(ah[mf], sA_addr(bAh, 144, wm * 32 + mf * 16, ks * 16, lane));
                ldm_x4(al[mf], sA_addr(bAl, 144, wm * 32 + mf * 16, ks * 16, lane));
            }
#pragma unroll
            for (int np = 0; np < 2; np++) {
                ldm_x4(bh[np], sB_addr(bBh, 144, wn * 32 + np * 16, ks * 16, lane));
                ldm_x4(bl[np], sB_addr(bBl, 144, wn * 32 + np * 16, ks * 16, lane));
            }
#pragma unroll
            for (int mf = 0; mf < 2; mf++)
#pragma unroll
                for (int nf = 0; nf < 4; nf++) {
                    const uint32_t* ph = &bh[nf >> 1][(nf & 1) * 2];
                    const uint32_t* pl = &bl[nf >> 1][(nf & 1) * 2];
                    mma16816(acc[mf][nf], ah[mf], ph);
                    mma16816(acc[mf][nf], ah[mf], pl);
                    mma16816(acc[mf][nf], al[mf], ph);
                }
        }
    }
#pragma unroll
    for (int mf = 0; mf < 2; mf++)
#pragma unroll
        for (int rr = 0; rr < 2; rr++) {
            int m = m0 + wm * 32 + mf * 16 + (lane >> 2) + rr * 8;
            float bi = bias[m];
            float* yo = Y + ((size_t)b * EM + m) * TT + t0 + wn * 32;
#pragma unroll
            for (int nf = 0; nf < 4; nf++) {
                float2 v = make_float2(acc[mf][nf][rr * 2] + bi, acc[mf][nf][rr * 2 + 1] + bi);
                *(float2*)(yo + nf * 8 + 2 * (lane & 3)) = v;
            }
        }
}

// ---------------- per-head LN + emit bf16 ----------------
__global__ void __launch_bounds__(256) ln_emit(
    const float* __restrict__ Y, const float* __restrict__ g, const float* __restrict__ be,
    __nv_bfloat16* __restrict__ oTD, __nv_bfloat16* __restrict__ oDT,
    const int* __restrict__ km, int mode) {
    __shared__ float sacc[64];
    int t = blockIdx.x * 256 + threadIdx.x, h = blockIdx.y, b = blockIdx.z;
    const float* base = Y + ((size_t)b * EM + h * 64) * TT + t;
    float v[64];
    float s = 0.f, s2 = 0.f;
#pragma unroll
    for (int d = 0; d < 64; d++) { v[d] = base[(size_t)d * TT]; s += v[d]; s2 += v[d] * v[d]; }
    float mu = s * (1.f / 64), var = s2 * (1.f / 64) - mu * mu, rs = rsqrtf(var + EPS);
#pragma unroll
    for (int d = 0; d < 64; d++) v[d] = (v[d] - mu) * rs * g[d] + be[d];
    if (mode == 0) {
        __nv_bfloat16* o = oTD + (((size_t)b * NH + h) * TT + t) * 64;
#pragma unroll
        for (int dd = 0; dd < 64; dd += 8) {
            uint32_t pk[4];
#pragma unroll
            for (int e = 0; e < 4; e++) {
                __nv_bfloat162 p = __floats2bfloat162_rn(v[dd + 2 * e], v[dd + 2 * e + 1]);
                pk[e] = *(uint32_t*)&p;
            }
            *(uint4*)(o + dd) = *(uint4*)pk;
        }
    } else {
        __nv_bfloat16* o = oDT + ((size_t)b * NH + h) * (size_t)(64 * TT) + t;
#pragma unroll
        for (int d = 0; d < 64; d++) o[(size_t)d * TT] = __float2bfloat16(v[d]);
        if (threadIdx.x < 64) sacc[threadIdx.x] = 0.f;
        __syncthreads();
        float w = (float)km[b * TT + t];
#pragma unroll
        for (int d = 0; d < 64; d++) {
            float x = v[d] * w;
            for (int off = 16; off; off >>= 1) x += __shfl_xor_sync(~0u, x, off);
            if ((threadIdx.x & 31) == 0) atomicAdd(&sacc[d], x);
        }
        __syncthreads();
        if (threadIdx.x < 64) atomicAdd(&g_Sv[((size_t)b * NH + h) * 64 + threadIdx.x], sacc[threadIdx.x]);
    }
}

// ---------------- fused attention (mma.sync, register-resident U) ----------------
// 128 threads, 4 warps; q-block 64. Warp w owns q rows [w*16, w*16+16) x all 128 k per chunk.
__global__ void __launch_bounds__(128, 3) attn_wmma(const int* __restrict__ qmask,
                                                    const int* __restrict__ kmask)
{
    extern __shared__ __align__(16) char smc[];
    __nv_bfloat16* sQ = (__nv_bfloat16*)smc;       // [64][72]
    __nv_bfloat16* sK = sQ + 64 * 72;              // [128][72]
    __nv_bfloat16* sV = sK + 128 * 72;             // [64][136]
    float* kms = (float*)(sV + 64 * 136);          // [128]
    uint32_t aQ = smem_u32(sQ), aK = smem_u32(sK), aV = smem_u32(sV);
    int tid = threadIdx.x, lane = tid & 31, wid = tid >> 5;
    int g = lane >> 2, tig = lane & 3;
    int q0 = blockIdx.x * 64;
    int b = blockIdx.y >> 3, h = blockIdx.y & 7;
    size_t hb = (size_t)(b * NH + h);
    const __nv_bfloat16* gQ = g_Qb + (hb * TT + q0) * 64;
    const __nv_bfloat16* gK = g_Kb + hb * TT * 64;
    const __nv_bfloat16* gV = g_Vb + hb * (size_t)(64 * TT);

    for (int idx = tid; idx < 512; idx += 128) {
        int r = idx >> 3, j = idx & 7;
        *(uint4*)(sQ + r * 72 + j * 8) = *(const uint4*)(gQ + (size_t)r * 64 + j * 8);
    }

    float oc[8][4] = {};
    float rs0 = 0.f, rs1 = 0.f;
    const float inv181 = 1.f / 181.f;

    for (int kc = 0; kc < 16; kc++) {
        int k0 = kc * 128;
        __syncthreads();
        for (int idx = tid; idx < 1024; idx += 128) {
            int r = idx >> 3, j = idx & 7;
            *(uint4*)(sK + r * 72 + j * 8) = *(const uint4*)(gK + (size_t)(k0 + r) * 64 + j * 8);
        }
        for (int idx = tid; idx < 1024; idx += 128) {
            int r = idx >> 4, j = idx & 15;
            *(uint4*)(sV + r * 136 + j * 8) = *(const uint4*)(gV + (size_t)r * TT + k0 + j * 8);
        }
        kms[tid] = (float)kmask[b * TT + k0 + tid];
        __syncthreads();

        // S = Q @ K^T : 16q x 128k per warp
        float sc[16][4] = {};
#pragma unroll
        for (int ks = 0; ks < 4; ks++) {
            uint32_t aq[4];
            ldm_x4(aq, sA_addr(aQ, 144, wid * 16, ks * 16, lane));
#pragma unroll
            for (int nb = 0; nb < 8; nb++) {
                uint32_t bk[4];
                ldm_x4(bk, sB_addr(aK, 144, nb * 16, ks * 16, lane));
                mma16816(sc[2 * nb], aq, &bk[0]);
                mma16816(sc[2 * nb + 1], aq, &bk[2]);
            }
        }

        // convert S -> U A-fragments in registers (accum layout == A-frag layout)
        uint32_t ua[8][4];
#pragma unroll
        for (int nf = 0; nf < 16; nf++) {
            int c0 = nf * 8 + 2 * tig;
            float k0f = kms[c0], k1f = kms[c0 + 1];
            float u0 = expm1p(sc[nf][0] * inv181) * k0f;
            float u1 = expm1p(sc[nf][1] * inv181) * k1f;
            float u2 = expm1p(sc[nf][2] * inv181) * k0f;
            float u3 = expm1p(sc[nf][3] * inv181) * k1f;
            rs0 += u0 + u1;
            rs1 += u2 + u3;
            __nv_bfloat162 p01 = __floats2bfloat162_rn(u0, u1);
            __nv_bfloat162 p23 = __floats2bfloat162_rn(u2, u3);
            int kk = nf >> 1, hi = (nf & 1) * 2;
            ua[kk][hi] = *(uint32_t*)&p01;
            ua[kk][hi + 1] = *(uint32_t*)&p23;
        }

        // O += U @ V^T : 16q x 64d
#pragma unroll
        for (int kk = 0; kk < 8; kk++) {
#pragma unroll
            for (int db = 0; db < 4; db++) {
                uint32_t bv[4];
                ldm_x4(bv, sB_addr(aV, 272, db * 16, kk * 16, lane));
                mma16816(oc[2 * db], ua[kk], &bv[0]);
                mma16816(oc[2 * db + 1], ua[kk], &bv[2]);
            }
        }
    }

    rs0 += __shfl_xor_sync(~0u, rs0, 1);
    rs0 += __shfl_xor_sync(~0u, rs0, 2);
    rs1 += __shfl_xor_sync(~0u, rs1, 1);
    rs1 += __shfl_xor_sync(~0u, rs1, 2);

    float nv = g_nv[b];
    const float* sv = g_Sv + hb * 64;
#pragma unroll
    for (int rr = 0; rr < 2; rr++) {
        int row = wid * 16 + g + rr * 8;
        int q = q0 + row;
        float l = nv + (rr ? rs1 : rs0);
        float inv = (qmask[b * TT + q] != 0) ? (1.f / l) : 0.f;
        __nv_bfloat16* oH = g_AoH + ((size_t)b * TT + q) * EM + h * 64;
        __nv_bfloat16* oL = g_AoL + ((size_t)b * TT + q) * EM + h * 64;
#pragma unroll
        for (int df = 0; df < 8; df++) {
            int d0 = df * 8 + 2 * tig;
            float x0 = (oc[df][rr * 2] + sv[d0]) * inv;
            float x1 = (oc[df][rr * 2 + 1] + sv[d0 + 1]) * inv;
            __nv_bfloat16 h0 = __float2bfloat16(x0), h1 = __float2bfloat16(x1);
            __nv_bfloat162 ph = __halves2bfloat162(h0, h1);
            __nv_bfloat162 pl = __floats2bfloat162_rn(x0 - __bfloat162float(h0),
                                                      x1 - __bfloat162float(h1));
            *(uint32_t*)(oH + d0) = *(uint32_t*)&ph;
            *(uint32_t*)(oL + d0) = *(uint32_t*)&pl;
        }
    }
}

// ---------------- launch ----------------
extern "C" void kernel_launch(void* const* d_in, const int* in_sizes, int n_in,
                              void* d_out, int out_size) {
    const float* q  = (const float*)d_in[0];
    const float* k  = (const float*)d_in[1];
    const float* v  = (const float*)d_in[2];
    const int* qm   = (const int*)d_in[3];
    const int* km   = (const int*)d_in[4];
    const int* vm   = (const int*)d_in[5];
    const float* W[4]  = {(const float*)d_in[6], (const float*)d_in[8], (const float*)d_in[10], (const float*)d_in[12]};
    const float* bi[4] = {(const float*)d_in[7], (const float*)d_in[9], (const float*)d_in[11], (const float*)d_in[13]};
    const float* lng[3] = {(const float*)d_in[14], (const float*)d_in[16], (const float*)d_in[18]};
    const float* lnb[3] = {(const float*)d_in[15], (const float*)d_in[17], (const float*)d_in[19]};
    float* out = (float*)d_out;

    void *pWH, *pWL, *pXH, *pXL, *pY, *pQ, *pK, *pV, *pAH, *pAL;
    cudaGetSymbolAddress(&pWH, g_WH); cudaGetSymbolAddress(&pWL, g_WL);
    cudaGetSymbolAddress(&pXH, g_XH); cudaGetSymbolAddress(&pXL, g_XL);
    cudaGetSymbolAddress(&pY, g_Yp);
    cudaGetSymbolAddress(&pQ, g_Qb); cudaGetSymbolAddress(&pK, g_Kb); cudaGetSymbolAddress(&pV, g_Vb);
    cudaGetSymbolAddress(&pAH, g_AoH); cudaGetSymbolAddress(&pAL, g_AoL);
    __nv_bfloat16* WH = (__nv_bfloat16*)pWH;
    __nv_bfloat16* WL = (__nv_bfloat16*)pWL;
    __nv_bfloat16* XH = (__nv_bfloat16*)pXH;
    __nv_bfloat16* XL = (__nv_bfloat16*)pXL;
    float* Yp = (float*)pY;

    const int PROJ_SMEM = (2 * 128 + 2 * 64) * 72 * 2;                   // 55296
    const int ATTN_SMEM = (64 * 72 + 128 * 72 + 64 * 136) * 2 + 128 * 4; // 45568
    cudaFuncSetAttribute(proj_wmma, cudaFuncAttributeMaxDynamicSharedMemorySize, PROJ_SMEM);
    cudaFuncSetAttribute(attn_wmma, cudaFuncAttributeMaxDynamicSharedMemorySize, ATTN_SMEM);

    prep_w4<<<dim3(EM, 4), 128>>>(W[0], W[1], W[2], W[3]);
    prep_x3<<<dim3(TT / 32, EM / 32, 3 * BB), dim3(32, 8)>>>(q, k, v, qm, km, vm);
    init_aux<<<BB, 256>>>(km);

    dim3 gp(TT / 64, EM / 128, BB);
    dim3 gl(TT / 256, NH, BB);
    for (int i = 0; i < 3; i++) {
        proj_wmma<<<gp, 256, PROJ_SMEM>>>(WH + (size_t)i * EM * EM, WL + (size_t)i * EM * EM,
                                          XH + (size_t)i * BB * TT * EM, XL + (size_t)i * BB * TT * EM,
                                          bi[i], Yp);
        if (i == 0)      ln_emit<<<gl, 256>>>(Yp, lng[0], lnb[0], (__nv_bfloat16*)pQ, nullptr, km, 0);
        else if (i == 1) ln_emit<<<gl, 256>>>(Yp, lng[1], lnb[1], (__nv_bfloat16*)pK, nullptr, km, 0);
        else             ln_emit<<<gl, 256>>>(Yp, lng[2], lnb[2], nullptr, (__nv_bfloat16*)pV, km, 1);
    }

    attn_wmma<<<dim3(TT / 64, BB * NH), 128, ATTN_SMEM>>>(qm, km);

    proj_wmma<<<gp, 256, PROJ_SMEM>>>(WH + (size_t)3 * EM * EM, WL + (size_t)3 * EM * EM,
                                      (__nv_bfloat16*)pAH, (__nv_bfloat16*)pAL, bi[3], out);
}

// round 10
// speedup vs baseline: 1.4693x; 1.2570x over previous
#include <cuda_runtime.h>
#include <cuda_bf16.h>
#include <cstdint>

#define BB 2
#define EM 512
#define NH 8
#define DH 64
#define TT 2048
#define EPS 1e-5f

// ---------------- scratch ----------------
__device__ __align__(256) __nv_bfloat16 g_WH[4][EM * EM];
__device__ __align__(256) __nv_bfloat16 g_WL[4][EM * EM];
__device__ __align__(256) __nv_bfloat16 g_XH[3][BB * TT * EM];
__device__ __align__(256) __nv_bfloat16 g_XL[3][BB * TT * EM];
__device__ __align__(256) float         g_Yp[BB * EM * TT];
__device__ __align__(256) __nv_bfloat16 g_Qb[BB * NH * TT * DH];
__device__ __align__(256) __nv_bfloat16 g_Kb[BB * NH * TT * DH];
__device__ __align__(256) __nv_bfloat16 g_Vb[BB * NH * DH * TT];
__device__ __align__(256) __nv_bfloat16 g_AoH[BB * TT * EM];
__device__ __align__(256) __nv_bfloat16 g_AoL[BB * TT * EM];
__device__ float g_Sv[BB * NH * DH];
__device__ float g_nv[BB];

// ---------------- helpers ----------------
__device__ __forceinline__ uint32_t smem_u32(const void* p) {
    uint32_t a;
    asm("{ .reg .u64 t; cvta.to.shared.u64 t, %1; cvt.u32.u64 %0, t; }" : "=r"(a) : "l"(p));
    return a;
}
__device__ __forceinline__ void cpa16(uint32_t s, const void* g) {
    asm volatile("cp.async.cg.shared.global [%0], [%1], 16;" :: "r"(s), "l"(g));
}
__device__ __forceinline__ void cpa4(uint32_t s, const void* g) {
    asm volatile("cp.async.ca.shared.global [%0], [%1], 4;" :: "r"(s), "l"(g));
}
#define CP_COMMIT() asm volatile("cp.async.commit_group;" ::: "memory")
#define CP_WAIT1()  asm volatile("cp.async.wait_group 1;" ::: "memory")

__device__ __forceinline__ void ldm_x4(uint32_t* r, uint32_t a) {
    asm volatile("ldmatrix.sync.aligned.m8n8.x4.shared.b16 {%0,%1,%2,%3}, [%4];"
                 : "=r"(r[0]), "=r"(r[1]), "=r"(r[2]), "=r"(r[3]) : "r"(a));
}

__device__ __forceinline__ void mma16816(float* c, const uint32_t* a, const uint32_t* b) {
    asm volatile(
        "mma.sync.aligned.m16n8k16.row.col.f32.bf16.bf16.f32 "
        "{%0,%1,%2,%3}, {%4,%5,%6,%7}, {%8,%9}, {%0,%1,%2,%3};"
        : "+f"(c[0]), "+f"(c[1]), "+f"(c[2]), "+f"(c[3])
        : "r"(a[0]), "r"(a[1]), "r"(a[2]), "r"(a[3]), "r"(b[0]), "r"(b[1]));
}

__device__ __forceinline__ uint32_t sA_addr(uint32_t base, int stride, int mo, int ko, int lane) {
    int j = lane >> 3, r = lane & 7;
    return base + (uint32_t)((mo + ((j & 1) << 3) + r) * stride + (ko + ((j >> 1) << 3)) * 2);
}
__device__ __forceinline__ uint32_t sB_addr(uint32_t base, int stride, int no, int ko, int lane) {
    int j = lane >> 3, r = lane & 7;
    return base + (uint32_t)((no + ((j >> 1) << 3) + r) * stride + (ko + ((j & 1) << 3)) * 2);
}

__device__ __forceinline__ float expm1p(float s) {
    float p = 1.f / 720.f;
    p = fmaf(p, s, 1.f / 120.f);
    p = fmaf(p, s, 1.f / 24.f);
    p = fmaf(p, s, 1.f / 6.f);
    p = fmaf(p, s, 0.5f);
    p = fmaf(p, s, 1.f);
    return p * s;
}

// ---------------- prep kernels ----------------
__global__ void __launch_bounds__(128) prep_w4(const float* __restrict__ W0,
                                               const float* __restrict__ W1,
                                               const float* __restrict__ W2,
                                               const float* __restrict__ W3) {
    __shared__ float red[8];
    const float* Ws[4] = {W0, W1, W2, W3};
    int i = blockIdx.y, row = blockIdx.x, tid = threadIdx.x;
    const float* wr = Ws[i] + (size_t)row * EM;
    __nv_bfloat16* WH = g_WH[i];
    __nv_bfloat16* WL = g_WL[i];
    float s = 0.f, s2 = 0.f;
    for (int c = tid; c < EM; c += 128) { float v = wr[c]; s += v; s2 += v * v; }
    for (int o = 16; o; o >>= 1) { s += __shfl_xor_sync(~0u, s, o); s2 += __shfl_xor_sync(~0u, s2, o); }
    if ((tid & 31) == 0) { red[tid >> 5] = s; red[4 + (tid >> 5)] = s2; }
    __syncthreads();
    s = red[0] + red[1] + red[2] + red[3];
    s2 = red[4] + red[5] + red[6] + red[7];
    float mu = s * (1.f / EM), var = s2 * (1.f / EM) - mu * mu, r = rsqrtf(var + EPS);
    for (int c = tid; c < EM; c += 128) {
        float wn = (wr[c] - mu) * r;
        __nv_bfloat16 h = __float2bfloat16(wn);
        WH[(size_t)row * EM + c] = h;
        WL[(size_t)row * EM + c] = __float2bfloat16(wn - __bfloat162float(h));
    }
}

__global__ void prep_x3(const float* __restrict__ x0, const float* __restrict__ x1,
                        const float* __restrict__ x2,
                        const int* __restrict__ m0, const int* __restrict__ m1,
                        const int* __restrict__ m2) {
    __shared__ float s[32][33];
    const float* Xs[3] = {x0, x1, x2};
    const int* Ms[3] = {m0, m1, m2};
    int which = blockIdx.z >> 1, b = blockIdx.z & 1;
    const float* X = Xs[which];
    const int* mask = Ms[which];
    __nv_bfloat16* XH = g_XH[which];
    __nv_bfloat16* XL = g_XL[which];
    int t0 = blockIdx.x * 32, i0 = blockIdx.y * 32;
    int tx = threadIdx.x, ty = threadIdx.y;
#pragma unroll
    for (int rr = 0; rr < 4; rr++)
        s[ty + 8 * rr][tx] = X[((size_t)b * EM + i0 + ty + 8 * rr) * TT + t0 + tx];
    __syncthreads();
#pragma unroll
    for (int rr = 0; rr < 4; rr++) {
        int tl = ty + 8 * rr, t = t0 + tl;
        float x = s[tx][tl] * (float)mask[b * TT + t];
        __nv_bfloat16 h = __float2bfloat16(x);
        size_t o = ((size_t)b * TT + t) * EM + i0 + tx;
        XH[o] = h;
        XL[o] = __float2bfloat16(x - __bfloat162float(h));
    }
}

__global__ void init_aux(const int* __restrict__ km) {
    __shared__ float red[8];
    int b = blockIdx.x, tid = threadIdx.x;
    for (int i = tid; i < NH * DH; i += 256) g_Sv[b * NH * DH + i] = 0.f;
    float c = 0.f;
    for (int t = tid; t < TT; t += 256) c += (float)km[b * TT + t];
    for (int o = 16; o; o >>= 1) c += __shfl_xor_sync(~0u, c, o);
    if ((tid & 31) == 0) red[tid >> 5] = c;
    __syncthreads();
    if (tid == 0) {
        float tt = 0.f;
        for (int w = 0; w < 8; w++) tt += red[w];
        g_nv[b] = tt;
    }
}

// ---------------- projection GEMM (cp.async 2-stage, mma.sync split-3) ----------------
// block tile 128m x 64t, 8 warps = 4m x 2t; stage = Ah(18432)+Al(18432)+Bh(9216)+Bl(9216)=55296
#define PSTG 55296
__global__ void __launch_bounds__(256) proj_wmma(
    const __nv_bfloat16* __restrict__ AH, const __nv_bfloat16* __restrict__ AL,
    const __nv_bfloat16* __restrict__ BH, const __nv_bfloat16* __restrict__ BL,
    const float* __restrict__ bias, float* __restrict__ Y)
{
    extern __shared__ __align__(16) char smc[];
    uint32_t sb = smem_u32(smc);
    int tid = threadIdx.x, lane = tid & 31, wid = tid >> 5;
    int wm = wid >> 1, wn = wid & 1;
    int t0 = blockIdx.x * 64, m0 = blockIdx.y * 128, b = blockIdx.z;
    const __nv_bfloat16* gAh = AH + (size_t)m0 * EM;
    const __nv_bfloat16* gAl = AL + (size_t)m0 * EM;
    const __nv_bfloat16* gBh = BH + ((size_t)b * TT + t0) * EM;
    const __nv_bfloat16* gBl = BL + ((size_t)b * TT + t0) * EM;

    auto issue = [&](int kc, int st) {
        int k0 = kc * 64;
        uint32_t base = sb + st * PSTG;
#pragma unroll
        for (int i = 0; i < 4; i++) {
            int idx = tid + i * 256;
            int r = idx >> 3, j = idx & 7;
            uint32_t off = (uint32_t)(r * 72 + j * 8) * 2;
            cpa16(base + off, gAh + (size_t)r * EM + k0 + j * 8);
            cpa16(base + 18432 + off, gAl + (size_t)r * EM + k0 + j * 8);
        }
#pragma unroll
        for (int i = 0; i < 2; i++) {
            int idx = tid + i * 256;
            int r = idx >> 3, j = idx & 7;
            uint32_t off = (uint32_t)(r * 72 + j * 8) * 2;
            cpa16(base + 36864 + off, gBh + (size_t)r * EM + k0 + j * 8);
            cpa16(base + 46080 + off, gBl + (size_t)r * EM + k0 + j * 8);
        }
    };

    issue(0, 0); CP_COMMIT();
    issue(1, 1); CP_COMMIT();

    float acc[2][4][4] = {};

    for (int kc = 0; kc < 8; kc++) {
        int st = kc & 1;
        CP_WAIT1();
        __syncthreads();
        uint32_t bAh = sb + st * PSTG, bAl = bAh + 18432, bBh = bAh + 36864, bBl = bAh + 46080;
#pragma unroll
        for (int ks = 0; ks < 4; ks++) {
            uint32_t ah[2][4], al[2][4], bh[2][4], bl[2][4];
#pragma unroll
            for (int mf = 0; mf < 2; mf++) {
                ldm_x4(ah[mf], sA_addr(bAh, 144, wm * 32 + mf * 16, ks * 16, lane));
                ldm_x4(al[mf], sA_addr(bAl, 144, wm * 32 + mf * 16, ks * 16, lane));
            }
#pragma unroll
            for (int np = 0; np < 2; np++) {
                ldm_x4(bh[np], sB_addr(bBh, 144, wn * 32 + np * 16, ks * 16, lane));
                ldm_x4(bl[np], sB_addr(bBl, 144, wn * 32 + np * 16, ks * 16, lane));
            }
#pragma unroll
            for (int mf = 0; mf < 2; mf++)
#pragma unroll
                for (int nf = 0; nf < 4; nf++) {
                    const uint32_t* ph = &bh[nf >> 1][(nf & 1) * 2];
                    const uint32_t* pl = &bl[nf >> 1][(nf & 1) * 2];
                    mma16816(acc[mf][nf], ah[mf], ph);
                    mma16816(acc[mf][nf], ah[mf], pl);
                    mma16816(acc[mf][nf], al[mf], ph);
                }
        }
        __syncthreads();
        if (kc + 2 < 8) issue(kc + 2, st);
        CP_COMMIT();
    }

#pragma unroll
    for (int mf = 0; mf < 2; mf++)
#pragma unroll
        for (int rr = 0; rr < 2; rr++) {
            int m = m0 + wm * 32 + mf * 16 + (lane >> 2) + rr * 8;
            float bi = bias[m];
            float* yo = Y + ((size_t)b * EM + m) * TT + t0 + wn * 32;
#pragma unroll
            for (int nf = 0; nf < 4; nf++) {
                float2 v = make_float2(acc[mf][nf][rr * 2] + bi, acc[mf][nf][rr * 2 + 1] + bi);
                *(float2*)(yo + nf * 8 + 2 * (lane & 3)) = v;
            }
        }
}

// ---------------- per-head LN + emit bf16 ----------------
__global__ void __launch_bounds__(256) ln_emit(
    const float* __restrict__ Y, const float* __restrict__ g, const float* __restrict__ be,
    __nv_bfloat16* __restrict__ oTD, __nv_bfloat16* __restrict__ oDT,
    const int* __restrict__ km, int mode) {
    __shared__ float sacc[64];
    int t = blockIdx.x * 256 + threadIdx.x, h = blockIdx.y, b = blockIdx.z;
    const float* base = Y + ((size_t)b * EM + h * 64) * TT + t;
    float v[64];
    float s = 0.f, s2 = 0.f;
#pragma unroll
    for (int d = 0; d < 64; d++) { v[d] = base[(size_t)d * TT]; s += v[d]; s2 += v[d] * v[d]; }
    float mu = s * (1.f / 64), var = s2 * (1.f / 64) - mu * mu, rs = rsqrtf(var + EPS);
#pragma unroll
    for (int d = 0; d < 64; d++) v[d] = (v[d] - mu) * rs * g[d] + be[d];
    if (mode == 0) {
        __nv_bfloat16* o = oTD + (((size_t)b * NH + h) * TT + t) * 64;
#pragma unroll
        for (int dd = 0; dd < 64; dd += 8) {
            uint32_t pk[4];
#pragma unroll
            for (int e = 0; e < 4; e++) {
                __nv_bfloat162 p = __floats2bfloat162_rn(v[dd + 2 * e], v[dd + 2 * e + 1]);
                pk[e] = *(uint32_t*)&p;
            }
            *(uint4*)(o + dd) = *(uint4*)pk;
        }
    } else {
        __nv_bfloat16* o = oDT + ((size_t)b * NH + h) * (size_t)(64 * TT) + t;
#pragma unroll
        for (int d = 0; d < 64; d++) o[(size_t)d * TT] = __float2bfloat16(v[d]);
        if (threadIdx.x < 64) sacc[threadIdx.x] = 0.f;
        __syncthreads();
        float w = (float)km[b * TT + t];
#pragma unroll
        for (int d = 0; d < 64; d++) {
            float x = v[d] * w;
            for (int off = 16; off; off >>= 1) x += __shfl_xor_sync(~0u, x, off);
            if ((threadIdx.x & 31) == 0) atomicAdd(&sacc[d], x);
        }
        __syncthreads();
        if (threadIdx.x < 64) atomicAdd(&g_Sv[((size_t)b * NH + h) * 64 + threadIdx.x], sacc[threadIdx.x]);
    }
}

// ---------------- fused attention (cp.async 2-stage, register-resident U) ----------------
// 128 threads, 4 warps, 64-q block. Stage = K(18432)+V(17408)=35840; Q at 0 (9216); kms int at 80896.
#define ASTG 35840
#define AQSZ 9216
#define AKMS 80896
__global__ void __launch_bounds__(128) attn_wmma(const int* __restrict__ qmask,
                                                 const int* __restrict__ kmask)
{
    extern __shared__ __align__(16) char smc[];
    uint32_t sb = smem_u32(smc);
    __nv_bfloat16* sQ = (__nv_bfloat16*)smc;
    uint32_t aQ = sb;
    int tid = threadIdx.x, lane = tid & 31, wid = tid >> 5;
    int g = lane >> 2, tig = lane & 3;
    int q0 = blockIdx.x * 64;
    int b = blockIdx.y >> 3, h = blockIdx.y & 7;
    size_t hb = (size_t)(b * NH + h);
    const __nv_bfloat16* gQ = g_Qb + (hb * TT + q0) * 64;
    const __nv_bfloat16* gK = g_Kb + hb * TT * 64;
    const __nv_bfloat16* gV = g_Vb + hb * (size_t)(64 * TT);

    auto issue = [&](int kc, int st) {
        int k0 = kc * 128;
        uint32_t base = sb + AQSZ + st * ASTG;
#pragma unroll
        for (int i = 0; i < 8; i++) {
            int idx = tid + i * 128;
            int r = idx >> 3, j = idx & 7;
            cpa16(base + (uint32_t)(r * 72 + j * 8) * 2, gK + (size_t)(k0 + r) * 64 + j * 8);
        }
#pragma unroll
        for (int i = 0; i < 8; i++) {
            int idx = tid + i * 128;
            int r = idx >> 4, j = idx & 15;
            cpa16(base + 18432 + (uint32_t)(r * 136 + j * 8) * 2, gV + (size_t)r * TT + k0 + j * 8);
        }
        cpa4(sb + AKMS + st * 512 + tid * 4, kmask + b * TT + k0 + tid);
    };

    for (int idx = tid; idx < 512; idx += 128) {
        int r = idx >> 3, j = idx & 7;
        *(uint4*)(sQ + r * 72 + j * 8) = *(const uint4*)(gQ + (size_t)r * 64 + j * 8);
    }

    issue(0, 0); CP_COMMIT();
    issue(1, 1); CP_COMMIT();

    float oc[8][4] = {};
    float rs0 = 0.f, rs1 = 0.f;
    const float inv181 = 1.f / 181.f;

    for (int kc = 0; kc < 16; kc++) {
        int st = kc & 1;
        CP_WAIT1();
        __syncthreads();
        uint32_t aK = sb + AQSZ + st * ASTG, aV = aK + 18432;
        const int* kmsi = (const int*)(smc + AKMS + st * 512);

        // S = Q @ K^T : 16q x 128k per warp
        float sc[16][4] = {};
#pragma unroll
        for (int ks = 0; ks < 4; ks++) {
            uint32_t aq[4];
            ldm_x4(aq, sA_addr(aQ, 144, wid * 16, ks * 16, lane));
#pragma unroll
            for (int nb = 0; nb < 8; nb++) {
                uint32_t bk[4];
                ldm_x4(bk, sB_addr(aK, 144, nb * 16, ks * 16, lane));
                mma16816(sc[2 * nb], aq, &bk[0]);
                mma16816(sc[2 * nb + 1], aq, &bk[2]);
            }
        }

        // convert S -> U A-fragments in registers
        uint32_t ua[8][4];
#pragma unroll
        for (int nf = 0; nf < 16; nf++) {
            int c0 = nf * 8 + 2 * tig;
            float k0f = (float)kmsi[c0], k1f = (float)kmsi[c0 + 1];
            float u0 = expm1p(sc[nf][0] * inv181) * k0f;
            float u1 = expm1p(sc[nf][1] * inv181) * k1f;
            float u2 = expm1p(sc[nf][2] * inv181) * k0f;
            float u3 = expm1p(sc[nf][3] * inv181) * k1f;
            rs0 += u0 + u1;
            rs1 += u2 + u3;
            __nv_bfloat162 p01 = __floats2bfloat162_rn(u0, u1);
            __nv_bfloat162 p23 = __floats2bfloat162_rn(u2, u3);
            int kk = nf >> 1, hi = (nf & 1) * 2;
            ua[kk][hi] = *(uint32_t*)&p01;
            ua[kk][hi + 1] = *(uint32_t*)&p23;
        }

        // O += U @ V^T : 16q x 64d
#pragma unroll
        for (int kk = 0; kk < 8; kk++) {
#pragma unroll
            for (int db = 0; db < 4; db++) {
                uint32_t bv[4];
                ldm_x4(bv, sB_addr(aV, 272, db * 16, kk * 16, lane));
                mma16816(oc[2 * db], ua[kk], &bv[0]);
                mma16816(oc[2 * db + 1], ua[kk], &bv[2]);
            }
        }
        __syncthreads();
        if (kc + 2 < 16) issue(kc + 2, st);
        CP_COMMIT();
    }

    rs0 += __shfl_xor_sync(~0u, rs0, 1);
    rs0 += __shfl_xor_sync(~0u, rs0, 2);
    rs1 += __shfl_xor_sync(~0u, rs1, 1);
    rs1 += __shfl_xor_sync(~0u, rs1, 2);

    float nv = g_nv[b];
    const float* sv = g_Sv + hb * 64;
#pragma unroll
    for (int rr = 0; rr < 2; rr++) {
        int row = wid * 16 + g + rr * 8;
        int q = q0 + row;
        float l = nv + (rr ? rs1 : rs0);
        float inv = (qmask[b * TT + q] != 0) ? (1.f / l) : 0.f;
        __nv_bfloat16* oH = g_AoH + ((size_t)b * TT + q) * EM + h * 64;
        __nv_bfloat16* oL = g_AoL + ((size_t)b * TT + q) * EM + h * 64;
#pragma unroll
        for (int df = 0; df < 8; df++) {
            int d0 = df * 8 + 2 * tig;
            float x0 = (oc[df][rr * 2] + sv[d0]) * inv;
            float x1 = (oc[df][rr * 2 + 1] + sv[d0 + 1]) * inv;
            __nv_bfloat16 h0 = __float2bfloat16(x0), h1 = __float2bfloat16(x1);
            __nv_bfloat162 ph = __halves2bfloat162(h0, h1);
            __nv_bfloat162 pl = __floats2bfloat162_rn(x0 - __bfloat162float(h0),
                                                      x1 - __bfloat162float(h1));
            *(uint32_t*)(oH + d0) = *(uint32_t*)&ph;
            *(uint32_t*)(oL + d0) = *(uint32_t*)&pl;
        }
    }
}

// ---------------- launch ----------------
extern "C" void kernel_launch(void* const* d_in, const int* in_sizes, int n_in,
                              void* d_out, int out_size) {
    const float* q  = (const float*)d_in[0];
    const float* k  = (const float*)d_in[1];
    const float* v  = (const float*)d_in[2];
    const int* qm   = (const int*)d_in[3];
    const int* km   = (const int*)d_in[4];
    const int* vm   = (const int*)d_in[5];
    const float* W[4]  = {(const float*)d_in[6], (const float*)d_in[8], (const float*)d_in[10], (const float*)d_in[12]};
    const float* bi[4] = {(const float*)d_in[7], (const float*)d_in[9], (const float*)d_in[11], (const float*)d_in[13]};
    const float* lng[3] = {(const float*)d_in[14], (const float*)d_in[16], (const float*)d_in[18]};
    const float* lnb[3] = {(const float*)d_in[15], (const float*)d_in[17], (const float*)d_in[19]};
    float* out = (float*)d_out;

    void *pWH, *pWL, *pXH, *pXL, *pY, *pQ, *pK, *pV, *pAH, *pAL;
    cudaGetSymbolAddress(&pWH, g_WH); cudaGetSymbolAddress(&pWL, g_WL);
    cudaGetSymbolAddress(&pXH, g_XH); cudaGetSymbolAddress(&pXL, g_XL);
    cudaGetSymbolAddress(&pY, g_Yp);
    cudaGetSymbolAddress(&pQ, g_Qb); cudaGetSymbolAddress(&pK, g_Kb); cudaGetSymbolAddress(&pV, g_Vb);
    cudaGetSymbolAddress(&pAH, g_AoH); cudaGetSymbolAddress(&pAL, g_AoL);
    __nv_bfloat16* WH = (__nv_bfloat16*)pWH;
    __nv_bfloat16* WL = (__nv_bfloat16*)pWL;
    __nv_bfloat16* XH = (__nv_bfloat16*)pXH;
    __nv_bfloat16* XL = (__nv_bfloat16*)pXL;
    float* Yp = (float*)pY;

    const int PROJ_SMEM = 2 * PSTG;            // 110592
    const int ATTN_SMEM = AKMS + 2 * 512;      // 81920
    cudaFuncSetAttribute(proj_wmma, cudaFuncAttributeMaxDynamicSharedMemorySize, PROJ_SMEM);
    cudaFuncSetAttribute(attn_wmma, cudaFuncAttributeMaxDynamicSharedMemorySize, ATTN_SMEM);

    prep_w4<<<dim3(EM, 4), 128>>>(W[0], W[1], W[2], W[3]);
    prep_x3<<<dim3(TT / 32, EM / 32, 3 * BB), dim3(32, 8)>>>(q, k, v, qm, km, vm);
    init_aux<<<BB, 256>>>(km);

    dim3 gp(TT / 64, EM / 128, BB);
    dim3 gl(TT / 256, NH, BB);
    for (int i = 0; i < 3; i++) {
        proj_wmma<<<gp, 256, PROJ_SMEM>>>(WH + (size_t)i * EM * EM, WL + (size_t)i * EM * EM,
                                          XH + (size_t)i * BB * TT * EM, XL + (size_t)i * BB * TT * EM,
                                          bi[i], Yp);
        if (i == 0)      ln_emit<<<gl, 256>>>(Yp, lng[0], lnb[0], (__nv_bfloat16*)pQ, nullptr, km, 0);
        else if (i == 1) ln_emit<<<gl, 256>>>(Yp, lng[1], lnb[1], (__nv_bfloat16*)pK, nullptr, km, 0);
        else             ln_emit<<<gl, 256>>>(Yp, lng[2], lnb[2], nullptr, (__nv_bfloat16*)pV, km, 1);
    }

    attn_wmma<<<dim3(TT / 64, BB * NH), 128, ATTN_SMEM>>>(qm, km);

    proj_wmma<<<gp, 256, PROJ_SMEM>>>(WH + (size_t)3 * EM * EM, WL + (size_t)3 * EM * EM,
                                      (__nv_bfloat16*)pAH, (__nv_bfloat16*)pAL, bi[3], out);
}

// round 12
// speedup vs baseline: 1.5782x; 1.0742x over previous
#include <cuda_runtime.h>
#include <cuda_bf16.h>
#include <cstdint>

#define BB 2
#define EM 512
#define NH 8
#define DH 64
#define TT 2048
#define EPS 1e-5f

// ---------------- scratch ----------------
__device__ __align__(256) __nv_bfloat16 g_WH[4][EM * EM];
__device__ __align__(256) __nv_bfloat16 g_WL[4][EM * EM];
__device__ __align__(256) __nv_bfloat16 g_XH[3][BB * TT * EM];
__device__ __align__(256) __nv_bfloat16 g_XL[3][BB * TT * EM];
__device__ __align__(256) __nv_bfloat16 g_Qb[BB * NH * TT * DH];
__device__ __align__(256) __nv_bfloat16 g_Kb[BB * NH * TT * DH];
__device__ __align__(256) __nv_bfloat16 g_Vb[BB * NH * DH * TT];
__device__ __align__(256) __nv_bfloat16 g_AoH[BB * TT * EM];
__device__ __align__(256) __nv_bfloat16 g_AoL[BB * TT * EM];
__device__ float g_Sv[BB * NH * DH];
__device__ float g_nv[BB];

// ---------------- helpers ----------------
__device__ __forceinline__ uint32_t smem_u32(const void* p) {
    uint32_t a;
    asm("{ .reg .u64 t; cvta.to.shared.u64 t, %1; cvt.u32.u64 %0, t; }" : "=r"(a) : "l"(p));
    return a;
}
__device__ __forceinline__ void cpa16(uint32_t s, const void* g) {
    asm volatile("cp.async.cg.shared.global [%0], [%1], 16;" :: "r"(s), "l"(g));
}
__device__ __forceinline__ void cpa4(uint32_t s, const void* g) {
    asm volatile("cp.async.ca.shared.global [%0], [%1], 4;" :: "r"(s), "l"(g));
}
#define CP_COMMIT() asm volatile("cp.async.commit_group;" ::: "memory")
#define CP_WAIT1()  asm volatile("cp.async.wait_group 1;" ::: "memory")

__device__ __forceinline__ void ldm_x4(uint32_t* r, uint32_t a) {
    asm volatile("ldmatrix.sync.aligned.m8n8.x4.shared.b16 {%0,%1,%2,%3}, [%4];"
                 : "=r"(r[0]), "=r"(r[1]), "=r"(r[2]), "=r"(r[3]) : "r"(a));
}

__device__ __forceinline__ void mma16816(float* c, const uint32_t* a, const uint32_t* b) {
    asm volatile(
        "mma.sync.aligned.m16n8k16.row.col.f32.bf16.bf16.f32 "
        "{%0,%1,%2,%3}, {%4,%5,%6,%7}, {%8,%9}, {%0,%1,%2,%3};"
        : "+f"(c[0]), "+f"(c[1]), "+f"(c[2]), "+f"(c[3])
        : "r"(a[0]), "r"(a[1]), "r"(a[2]), "r"(a[3]), "r"(b[0]), "r"(b[1]));
}

__device__ __forceinline__ uint32_t sA_addr(uint32_t base, int stride, int mo, int ko, int lane) {
    int j = lane >> 3, r = lane & 7;
    return base + (uint32_t)((mo + ((j & 1) << 3) + r) * stride + (ko + ((j >> 1) << 3)) * 2);
}
__device__ __forceinline__ uint32_t sB_addr(uint32_t base, int stride, int no, int ko, int lane) {
    int j = lane >> 3, r = lane & 7;
    return base + (uint32_t)((no + ((j >> 1) << 3) + r) * stride + (ko + ((j & 1) << 3)) * 2);
}

__device__ __forceinline__ float expm1p(float s) {
    float p = 1.f / 720.f;
    p = fmaf(p, s, 1.f / 120.f);
    p = fmaf(p, s, 1.f / 24.f);
    p = fmaf(p, s, 1.f / 6.f);
    p = fmaf(p, s, 0.5f);
    p = fmaf(p, s, 1.f);
    return p * s;
}

// ---------------- prep kernels ----------------
__global__ void __launch_bounds__(128) prep_w4(const float* __restrict__ W0,
                                               const float* __restrict__ W1,
                                               const float* __restrict__ W2,
                                               const float* __restrict__ W3) {
    __shared__ float red[8];
    const float* Ws[4] = {W0, W1, W2, W3};
    int i = blockIdx.y, row = blockIdx.x, tid = threadIdx.x;
    const float* wr = Ws[i] + (size_t)row * EM;
    __nv_bfloat16* WH = g_WH[i];
    __nv_bfloat16* WL = g_WL[i];
    float s = 0.f, s2 = 0.f;
    for (int c = tid; c < EM; c += 128) { float v = wr[c]; s += v; s2 += v * v; }
    for (int o = 16; o; o >>= 1) { s += __shfl_xor_sync(~0u, s, o); s2 += __shfl_xor_sync(~0u, s2, o); }
    if ((tid & 31) == 0) { red[tid >> 5] = s; red[4 + (tid >> 5)] = s2; }
    __syncthreads();
    s = red[0] + red[1] + red[2] + red[3];
    s2 = red[4] + red[5] + red[6] + red[7];
    float mu = s * (1.f / EM), var = s2 * (1.f / EM) - mu * mu, r = rsqrtf(var + EPS);
    for (int c = tid; c < EM; c += 128) {
        float wn = (wr[c] - mu) * r;
        __nv_bfloat16 h = __float2bfloat16(wn);
        WH[(size_t)row * EM + c] = h;
        WL[(size_t)row * EM + c] = __float2bfloat16(wn - __bfloat162float(h));
    }
}

__global__ void prep_x3(const float* __restrict__ x0, const float* __restrict__ x1,
                        const float* __restrict__ x2,
                        const int* __restrict__ m0, const int* __restrict__ m1,
                        const int* __restrict__ m2) {
    __shared__ float s[32][33];
    const float* Xs[3] = {x0, x1, x2};
    const int* Ms[3] = {m0, m1, m2};
    int which = blockIdx.z >> 1, b = blockIdx.z & 1;
    const float* X = Xs[which];
    const int* mask = Ms[which];
    __nv_bfloat16* XH = g_XH[which];
    __nv_bfloat16* XL = g_XL[which];
    int t0 = blockIdx.x * 32, i0 = blockIdx.y * 32;
    int tx = threadIdx.x, ty = threadIdx.y;
#pragma unroll
    for (int rr = 0; rr < 4; rr++)
        s[ty + 8 * rr][tx] = X[((size_t)b * EM + i0 + ty + 8 * rr) * TT + t0 + tx];
    __syncthreads();
#pragma unroll
    for (int rr = 0; rr < 4; rr++) {
        int tl = ty + 8 * rr, t = t0 + tl;
        float x = s[tx][tl] * (float)mask[b * TT + t];
        __nv_bfloat16 h = __float2bfloat16(x);
        size_t o = ((size_t)b * TT + t) * EM + i0 + tx;
        XH[o] = h;
        XL[o] = __float2bfloat16(x - __bfloat162float(h));
    }
}

__global__ void init_aux(const int* __restrict__ km) {
    __shared__ float red[8];
    int b = blockIdx.x, tid = threadIdx.x;
    for (int i = tid; i < NH * DH; i += 256) g_Sv[b * NH * DH + i] = 0.f;
    float c = 0.f;
    for (int t = tid; t < TT; t += 256) c += (float)km[b * TT + t];
    for (int o = 16; o; o >>= 1) c += __shfl_xor_sync(~0u, c, o);
    if ((tid & 31) == 0) red[tid >> 5] = c;
    __syncthreads();
    if (tid == 0) {
        float tt = 0.f;
        for (int w = 0; w < 8; w++) tt += red[w];
        g_nv[b] = tt;
    }
}

// ---------------- projection GEMM + fused LN epilogue ----------------
// block tile 128m x 64t, K-chunk 32, 3-stage cp.async ring, ONE sync/chunk, 2 CTAs/SM.
// Row stride 80 B (16-aligned; 8-row ldmatrix phases tile all 32 banks).
// Stage: Ah[128]@0, Al@10240, Bh[64]@20480, Bl@25600; stage = 30720 B x 3.
// mode 0: LN -> oTD [b][h][t][64] (Q/K). mode 1: LN -> oDT [b][h][d][T] + Sv (V). mode 2: fp32 + bias.
#define PSTR 80
#define PSTG 30720
#define PSY_F 65
__global__ void __launch_bounds__(256, 2) proj_fused(
    const __nv_bfloat16* __restrict__ AH, const __nv_bfloat16* __restrict__ AL,
    const __nv_bfloat16* __restrict__ BH, const __nv_bfloat16* __restrict__ BL,
    const float* __restrict__ bias,
    const float* __restrict__ lng, const float* __restrict__ lnb,
    __nv_bfloat16* __restrict__ oTD, __nv_bfloat16* __restrict__ oDT,
    float* __restrict__ Yout, const int* __restrict__ km, int mode)
{
    extern __shared__ __align__(16) char smc[];
    uint32_t sb = smem_u32(smc);
    int tid = threadIdx.x, lane = tid & 31, wid = tid >> 5;
    int g = lane >> 2, tig = lane & 3;
    int wm = wid >> 1, wn = wid & 1;
    int t0 = blockIdx.x * 64, m0 = blockIdx.y * 128, b = blockIdx.z;
    const __nv_bfloat16* gAh = AH + (size_t)m0 * EM;
    const __nv_bfloat16* gAl = AL + (size_t)m0 * EM;
    const __nv_bfloat16* gBh = BH + ((size_t)b * TT + t0) * EM;
    const __nv_bfloat16* gBl = BL + ((size_t)b * TT + t0) * EM;

    auto issue = [&](int kc, int st) {
        int k0 = kc * 32;
        uint32_t base = sb + st * PSTG;
#pragma unroll
        for (int i = 0; i < 2; i++) {
            int idx = tid + i * 256;
            int r = idx >> 2, j = idx & 3;
            uint32_t off = (uint32_t)(r * PSTR + j * 16);
            cpa16(base + off, gAh + (size_t)r * EM + k0 + j * 8);
            cpa16(base + 10240 + off, gAl + (size_t)r * EM + k0 + j * 8);
        }
        {
            int r = tid >> 2, j = tid & 3;
            uint32_t off = (uint32_t)(r * PSTR + j * 16);
            cpa16(base + 20480 + off, gBh + (size_t)r * EM + k0 + j * 8);
            cpa16(base + 25600 + off, gBl + (size_t)r * EM + k0 + j * 8);
        }
    };

    issue(0, 0); CP_COMMIT();
    issue(1, 1); CP_COMMIT();

    float acc[2][4][4] = {};

    for (int kc = 0; kc < 16; kc++) {
        int st = kc % 3;
        CP_WAIT1();
        __syncthreads();
        uint32_t bAh = sb + st * PSTG, bAl = bAh + 10240, bBh = bAh + 20480, bBl = bAh + 25600;
#pragma unroll
        for (int ks = 0; ks < 2; ks++) {
            uint32_t ah[2][4], al[2][4], bh[2][4], bl[2][4];
#pragma unroll
            for (int mf = 0; mf < 2; mf++) {
                ldm_x4(ah[mf], sA_addr(bAh, PSTR, wm * 32 + mf * 16, ks * 16, lane));
                ldm_x4(al[mf], sA_addr(bAl, PSTR, wm * 32 + mf * 16, ks * 16, lane));
            }
#pragma unroll
            for (int np = 0; np < 2; np++) {
                ldm_x4(bh[np], sB_addr(bBh, PSTR, wn * 32 + np * 16, ks * 16, lane));
                ldm_x4(bl[np], sB_addr(bBl, PSTR, wn * 32 + np * 16, ks * 16, lane));
            }
#pragma unroll
            for (int mf = 0; mf < 2; mf++)
#pragma unroll
                for (int nf = 0; nf < 4; nf++) {
                    const uint32_t* ph = &bh[nf >> 1][(nf & 1) * 2];
                    const uint32_t* pl = &bl[nf >> 1][(nf & 1) * 2];
                    mma16816(acc[mf][nf], ah[mf], ph);
                    mma16816(acc[mf][nf], ah[mf], pl);
                    mma16816(acc[mf][nf], al[mf], ph);
                }
        }
        if (kc + 2 < 16) issue(kc + 2, (kc + 2) % 3);
        CP_COMMIT();
    }

    if (mode == 2) {
#pragma unroll
        for (int mf = 0; mf < 2; mf++)
#pragma unroll
            for (int rr = 0; rr < 2; rr++) {
                int m = m0 + wm * 32 + mf * 16 + g + rr * 8;
                float bi = bias[m];
                float* yo = Yout + ((size_t)b * EM + m) * TT + t0 + wn * 32;
#pragma unroll
                for (int nf = 0; nf < 4; nf++) {
                    float2 v = make_float2(acc[mf][nf][rr * 2] + bi, acc[mf][nf][rr * 2 + 1] + bi);
                    *(float2*)(yo + nf * 8 + 2 * tig) = v;
                }
            }
        return;
    }

    // ---- fused LN epilogue ----
    float* sY = (float*)smc;                       // [128][65] fp32
    float* sSvW = (float*)(smc + 128 * PSY_F * 4); // [4][64]
    __syncthreads();  // all ldmatrix reads done; safe to overwrite stages
#pragma unroll
    for (int mf = 0; mf < 2; mf++)
#pragma unroll
        for (int rr = 0; rr < 2; rr++) {
            int m = wm * 32 + mf * 16 + g + rr * 8;
            float bi = bias[m0 + m];
#pragma unroll
            for (int nf = 0; nf < 4; nf++) {
                int t = wn * 32 + nf * 8 + 2 * tig;
                sY[m * PSY_F + t] = acc[mf][nf][rr * 2] + bi;
                sY[m * PSY_F + t + 1] = acc[mf][nf][rr * 2 + 1] + bi;
            }
        }
    __syncthreads();

    if (tid < 128) {
        int hh = tid >> 6, tl = tid & 63;
        int t = t0 + tl;
        int h = (m0 >> 6) + hh;
        float v[64];
        float s = 0.f, s2 = 0.f;
#pragma unroll
        for (int d = 0; d < 64; d++) {
            v[d] = sY[(hh * 64 + d) * PSY_F + tl];
            s += v[d]; s2 += v[d] * v[d];
        }
        float mu = s * (1.f / 64), var = s2 * (1.f / 64) - mu * mu, rs = rsqrtf(var + EPS);
#pragma unroll
        for (int d = 0; d < 64; d++) v[d] = (v[d] - mu) * rs * lng[d] + lnb[d];

        if (mode == 0) {
            __nv_bfloat16* o = oTD + (((size_t)b * NH + h) * TT + t) * 64;
#pragma unroll
            for (int dd = 0; dd < 64; dd += 8) {
                uint32_t pk[4];
#pragma unroll
                for (int e = 0; e < 4; e++) {
                    __nv_bfloat162 p = __floats2bfloat162_rn(v[dd + 2 * e], v[dd + 2 * e + 1]);
                    pk[e] = *(uint32_t*)&p;
                }
                *(uint4*)(o + dd) = *(uint4*)pk;
            }
        } else {
            __nv_bfloat16* o = oDT + ((size_t)b * NH + h) * (size_t)(64 * TT) + t;
#pragma unroll
            for (int d = 0; d < 64; d++) o[(size_t)d * TT] = __float2bfloat16(v[d]);
            float w = (float)km[b * TT + t];
#pragma unroll
            for (int d = 0; d < 64; d++) {
                float x = v[d] * w;
                for (int off = 16; off; off >>= 1) x += __shfl_xor_sync(~0u, x, off);
                if (lane == 0) sSvW[wid * 64 + d] = x;
            }
        }
    }
    if (mode == 1) {
        __syncthreads();
        if (tid < 128) {
            int hh = tid >> 6, d = tid & 63;
            float val = sSvW[(hh * 2) * 64 + d] + sSvW[(hh * 2 + 1) * 64 + d];
            atomicAdd(&g_Sv[((size_t)b * NH + (m0 >> 6) + hh) * 64 + d], val);
        }
    }
}

// ---------------- fused attention (cp.async 2-stage, register-resident U) ----------------
#define ASTG 35840
#define AQSZ 9216
#define AKMS 80896
__global__ void __launch_bounds__(128) attn_wmma(const int* __restrict__ qmask,
                                                 const int* __restrict__ kmask)
{
    extern __shared__ __align__(16) char smc[];
    uint32_t sb = smem_u32(smc);
    __nv_bfloat16* sQ = (__nv_bfloat16*)smc;
    uint32_t aQ = sb;
    int tid = threadIdx.x, lane = tid & 31, wid = tid >> 5;
    int g = lane >> 2, tig = lane & 3;
    int q0 = blockIdx.x * 64;
    int b = blockIdx.y >> 3, h = blockIdx.y & 7;
    size_t hb = (size_t)(b * NH + h);
    const __nv_bfloat16* gQ = g_Qb + (hb * TT + q0) * 64;
    const __nv_bfloat16* gK = g_Kb + hb * TT * 64;
    const __nv_bfloat16* gV = g_Vb + hb * (size_t)(64 * TT);

    auto issue = [&](int kc, int st) {
        int k0 = kc * 128;
        uint32_t base = sb + AQSZ + st * ASTG;
#pragma unroll
        for (int i = 0; i < 8; i++) {
            int idx = tid + i * 128;
            int r = idx >> 3, j = idx & 7;
            cpa16(base + (uint32_t)(r * 72 + j * 8) * 2, gK + (size_t)(k0 + r) * 64 + j * 8);
        }
#pragma unroll
        for (int i = 0; i < 8; i++) {
            int idx = tid + i * 128;
            int r = idx >> 4, j = idx & 15;
            cpa16(base + 18432 + (uint32_t)(r * 136 + j * 8) * 2, gV + (size_t)r * TT + k0 + j * 8);
        }
        cpa4(sb + AKMS + st * 512 + tid * 4, kmask + b * TT + k0 + tid);
    };

    for (int idx = tid; idx < 512; idx += 128) {
        int r = idx >> 3, j = idx & 7;
        *(uint4*)(sQ + r * 72 + j * 8) = *(const uint4*)(gQ + (size_t)r * 64 + j * 8);
    }

    issue(0, 0); CP_COMMIT();
    issue(1, 1); CP_COMMIT();

    float oc[8][4] = {};
    float rs0 = 0.f, rs1 = 0.f;
    const float inv181 = 1.f / 181.f;

    for (int kc = 0; kc < 16; kc++) {
        int st = kc & 1;
        CP_WAIT1();
        __syncthreads();
        uint32_t aK = sb + AQSZ + st * ASTG, aV = aK + 18432;
        const int* kmsi = (const int*)(smc + AKMS + st * 512);

        float sc[16][4] = {};
#pragma unroll
        for (int ks = 0; ks < 4; ks++) {
            uint32_t aq[4];
            ldm_x4(aq, sA_addr(aQ, 144, wid * 16, ks * 16, lane));
#pragma unroll
            for (int nb = 0; nb < 8; nb++) {
                uint32_t bk[4];
                ldm_x4(bk, sB_addr(aK, 144, nb * 16, ks * 16, lane));
                mma16816(sc[2 * nb], aq, &bk[0]);
                mma16816(sc[2 * nb + 1], aq, &bk[2]);
            }
        }

        uint32_t ua[8][4];
#pragma unroll
        for (int nf = 0; nf < 16; nf++) {
            int c0 = nf * 8 + 2 * tig;
            float k0f = (float)kmsi[c0], k1f = (float)kmsi[c0 + 1];
            float u0 = expm1p(sc[nf][0] * inv181) * k0f;
            float u1 = expm1p(sc[nf][1] * inv181) * k1f;
            float u2 = expm1p(sc[nf][2] * inv181) * k0f;
            float u3 = expm1p(sc[nf][3] * inv181) * k1f;
            rs0 += u0 + u1;
            rs1 += u2 + u3;
            __nv_bfloat162 p01 = __floats2bfloat162_rn(u0, u1);
            __nv_bfloat162 p23 = __floats2bfloat162_rn(u2, u3);
            int kk = nf >> 1, hi = (nf & 1) * 2;
            ua[kk][hi] = *(uint32_t*)&p01;
            ua[kk][hi + 1] = *(uint32_t*)&p23;
        }

#pragma unroll
        for (int kk = 0; kk < 8; kk++) {
#pragma unroll
            for (int db = 0; db < 4; db++) {
                uint32_t bv[4];
                ldm_x4(bv, sB_addr(aV, 272, db * 16, kk * 16, lane));
                mma16816(oc[2 * db], ua[kk], &bv[0]);
                mma16816(oc[2 * db + 1], ua[kk], &bv[2]);
            }
        }
        __syncthreads();
        if (kc + 2 < 16) issue(kc + 2, st);
        CP_COMMIT();
    }

    rs0 += __shfl_xor_sync(~0u, rs0, 1);
    rs0 += __shfl_xor_sync(~0u, rs0, 2);
    rs1 += __shfl_xor_sync(~0u, rs1, 1);
    rs1 += __shfl_xor_sync(~0u, rs1, 2);

    float nv = g_nv[b];
    const float* sv = g_Sv + hb * 64;
#pragma unroll
    for (int rr = 0; rr < 2; rr++) {
        int row = wid * 16 + g + rr * 8;
        int q = q0 + row;
        float l = nv + (rr ? rs1 : rs0);
        float inv = (qmask[b * TT + q] != 0) ? (1.f / l) : 0.f;
        __nv_bfloat16* oH = g_AoH + ((size_t)b * TT + q) * EM + h * 64;
        __nv_bfloat16* oL = g_AoL + ((size_t)b * TT + q) * EM + h * 64;
#pragma unroll
        for (int df = 0; df < 8; df++) {
            int d0 = df * 8 + 2 * tig;
            float x0 = (oc[df][rr * 2] + sv[d0]) * inv;
            float x1 = (oc[df][rr * 2 + 1] + sv[d0 + 1]) * inv;
            __nv_bfloat16 h0 = __float2bfloat16(x0), h1 = __float2bfloat16(x1);
            __nv_bfloat162 ph = __halves2bfloat162(h0, h1);
            __nv_bfloat162 pl = __floats2bfloat162_rn(x0 - __bfloat162float(h0),
                                                      x1 - __bfloat162float(h1));
            *(uint32_t*)(oH + d0) = *(uint32_t*)&ph;
            *(uint32_t*)(oL + d0) = *(uint32_t*)&pl;
        }
    }
}

// ---------------- launch ----------------
extern "C" void kernel_launch(void* const* d_in, const int* in_sizes, int n_in,
                              void* d_out, int out_size) {
    const float* q  = (const float*)d_in[0];
    const float* k  = (const float*)d_in[1];
    const float* v  = (const float*)d_in[2];
    const int* qm   = (const int*)d_in[3];
    const int* km   = (const int*)d_in[4];
    const int* vm   = (const int*)d_in[5];
    const float* W[4]  = {(const float*)d_in[6], (const float*)d_in[8], (const float*)d_in[10], (const float*)d_in[12]};
    const float* bi[4] = {(const float*)d_in[7], (const float*)d_in[9], (const float*)d_in[11], (const float*)d_in[13]};
    const float* lng[3] = {(const float*)d_in[14], (const float*)d_in[16], (const float*)d_in[18]};
    const float* lnb[3] = {(const float*)d_in[15], (const float*)d_in[17], (const float*)d_in[19]};
    float* out = (float*)d_out;

    void *pWH, *pWL, *pXH, *pXL, *pQ, *pK, *pV, *pAH, *pAL;
    cudaGetSymbolAddress(&pWH, g_WH); cudaGetSymbolAddress(&pWL, g_WL);
    cudaGetSymbolAddress(&pXH, g_XH); cudaGetSymbolAddress(&pXL, g_XL);
    cudaGetSymbolAddress(&pQ, g_Qb); cudaGetSymbolAddress(&pK, g_Kb); cudaGetSymbolAddress(&pV, g_Vb);
    cudaGetSymbolAddress(&pAH, g_AoH); cudaGetSymbolAddress(&pAL, g_AoL);
    __nv_bfloat16* WH = (__nv_bfloat16*)pWH;
    __nv_bfloat16* WL = (__nv_bfloat16*)pWL;
    __nv_bfloat16* XH = (__nv_bfloat16*)pXH;
    __nv_bfloat16* XL = (__nv_bfloat16*)pXL;

    const int PROJ_SMEM = 3 * PSTG + 1024;     // 93184
    const int ATTN_SMEM = AKMS + 2 * 512;      // 81920
    cudaFuncSetAttribute(proj_fused, cudaFuncAttributeMaxDynamicSharedMemorySize, PROJ_SMEM);
    cudaFuncSetAttribute(attn_wmma, cudaFuncAttributeMaxDynamicSharedMemorySize, ATTN_SMEM);

    prep_w4<<<dim3(EM, 4), 128>>>(W[0], W[1], W[2], W[3]);
    prep_x3<<<dim3(TT / 32, EM / 32, 3 * BB), dim3(32, 8)>>>(q, k, v, qm, km, vm);
    init_aux<<<BB, 256>>>(km);

    dim3 gp(TT / 64, EM / 128, BB);
    proj_fused<<<gp, 256, PROJ_SMEM>>>(WH + (size_t)0 * EM * EM, WL + (size_t)0 * EM * EM,
                                       XH + (size_t)0 * BB * TT * EM, XL + (size_t)0 * BB * TT * EM,
                                       bi[0], lng[0], lnb[0],
                                       (__nv_bfloat16*)pQ, nullptr, nullptr, km, 0);
    proj_fused<<<gp, 256, PROJ_SMEM>>>(WH + (size_t)1 * EM * EM, WL + (size_t)1 * EM * EM,
                                       XH + (size_t)1 * BB * TT * EM, XL + (size_t)1 * BB * TT * EM,
                                       bi[1], lng[1], lnb[1],
                                       (__nv_bfloat16*)pK, nullptr, nullptr, km, 0);
    proj_fused<<<gp, 256, PROJ_SMEM>>>(WH + (size_t)2 * EM * EM, WL + (size_t)2 * EM * EM,
                                       XH + (size_t)2 * BB * TT * EM, XL + (size_t)2 * BB * TT * EM,
                                       bi[2], lng[2], lnb[2],
                                       nullptr, (__nv_bfloat16*)pV, nullptr, km, 1);

    attn_wmma<<<dim3(TT / 64, BB * NH), 128, ATTN_SMEM>>>(qm, km);

    proj_fused<<<gp, 256, PROJ_SMEM>>>(WH + (size_t)3 * EM * EM, WL + (size_t)3 * EM * EM,
                                       (__nv_bfloat16*)pAH, (__nv_bfloat16*)pAL,
                                       bi[3], nullptr, nullptr,
                                       nullptr, nullptr, out, km, 2);
}

// round 14
// speedup vs baseline: 1.8515x; 1.1732x over previous
#include <cuda_runtime.h>
#include <cuda_fp16.h>
#include <cstdint>

#define BB 2
#define EM 512
#define NH 8
#define DH 64
#define TT 2048
#define EPS 1e-5f

// ---------------- scratch ----------------
__device__ __align__(256) __half g_WH[4][EM * EM];
__device__ __align__(256) __half g_XH[3][BB * TT * EM];
__device__ __align__(256) __half g_XL[3][BB * TT * EM];
__device__ __align__(256) __half g_Qb[BB * NH * TT * DH];
__device__ __align__(256) __half g_Kb[BB * NH * TT * DH];
__device__ __align__(256) __half g_Vb[BB * NH * DH * TT];
__device__ __align__(256) __half g_AoH[BB * TT * EM];
__device__ __align__(256) __half g_AoL[BB * TT * EM];
__device__ float g_Sv[BB * NH * DH];
__device__ float g_nv[BB];

// ---------------- helpers ----------------
__device__ __forceinline__ uint32_t smem_u32(const void* p) {
    uint32_t a;
    asm("{ .reg .u64 t; cvta.to.shared.u64 t, %1; cvt.u32.u64 %0, t; }" : "=r"(a) : "l"(p));
    return a;
}
__device__ __forceinline__ void cpa16(uint32_t s, const void* g) {
    asm volatile("cp.async.cg.shared.global [%0], [%1], 16;" :: "r"(s), "l"(g));
}
__device__ __forceinline__ void cpa4(uint32_t s, const void* g) {
    asm volatile("cp.async.ca.shared.global [%0], [%1], 4;" :: "r"(s), "l"(g));
}
#define CP_COMMIT() asm volatile("cp.async.commit_group;" ::: "memory")
#define CP_WAIT1()  asm volatile("cp.async.wait_group 1;" ::: "memory")
#define CP_WAIT2()  asm volatile("cp.async.wait_group 2;" ::: "memory")

__device__ __forceinline__ void ldm_x4(uint32_t* r, uint32_t a) {
    asm volatile("ldmatrix.sync.aligned.m8n8.x4.shared.b16 {%0,%1,%2,%3}, [%4];"
                 : "=r"(r[0]), "=r"(r[1]), "=r"(r[2]), "=r"(r[3]) : "r"(a));
}

__device__ __forceinline__ void mma16816(float* c, const uint32_t* a, const uint32_t* b) {
    asm volatile(
        "mma.sync.aligned.m16n8k16.row.col.f32.f16.f16.f32 "
        "{%0,%1,%2,%3}, {%4,%5,%6,%7}, {%8,%9}, {%0,%1,%2,%3};"
        : "+f"(c[0]), "+f"(c[1]), "+f"(c[2]), "+f"(c[3])
        : "r"(a[0]), "r"(a[1]), "r"(a[2]), "r"(a[3]), "r"(b[0]), "r"(b[1]));
}

__device__ __forceinline__ uint32_t sA_addr(uint32_t base, int stride, int mo, int ko, int lane) {
    int j = lane >> 3, r = lane & 7;
    return base + (uint32_t)((mo + ((j & 1) << 3) + r) * stride + (ko + ((j >> 1) << 3)) * 2);
}
__device__ __forceinline__ uint32_t sB_addr(uint32_t base, int stride, int no, int ko, int lane) {
    int j = lane >> 3, r = lane & 7;
    return base + (uint32_t)((no + ((j >> 1) << 3) + r) * stride + (ko + ((j & 1) << 3)) * 2);
}

__device__ __forceinline__ float expm1p(float s) {
    float p = 1.f / 720.f;
    p = fmaf(p, s, 1.f / 120.f);
    p = fmaf(p, s, 1.f / 24.f);
    p = fmaf(p, s, 1.f / 6.f);
    p = fmaf(p, s, 0.5f);
    p = fmaf(p, s, 1.f);
    return p * s;
}

// ---------------- prep kernels ----------------
__global__ void __launch_bounds__(128) prep_w4(const float* __restrict__ W0,
                                               const float* __restrict__ W1,
                                               const float* __restrict__ W2,
                                               const float* __restrict__ W3) {
    __shared__ float red[8];
    const float* Ws[4] = {W0, W1, W2, W3};
    int i = blockIdx.y, row = blockIdx.x, tid = threadIdx.x;
    const float* wr = Ws[i] + (size_t)row * EM;
    __half* WH = g_WH[i];
    float s = 0.f, s2 = 0.f;
    for (int c = tid; c < EM; c += 128) { float v = wr[c]; s += v; s2 += v * v; }
    for (int o = 16; o; o >>= 1) { s += __shfl_xor_sync(~0u, s, o); s2 += __shfl_xor_sync(~0u, s2, o); }
    if ((tid & 31) == 0) { red[tid >> 5] = s; red[4 + (tid >> 5)] = s2; }
    __syncthreads();
    s = red[0] + red[1] + red[2] + red[3];
    s2 = red[4] + red[5] + red[6] + red[7];
    float mu = s * (1.f / EM), var = s2 * (1.f / EM) - mu * mu, r = rsqrtf(var + EPS);
    for (int c = tid; c < EM; c += 128)
        WH[(size_t)row * EM + c] = __float2half_rn((wr[c] - mu) * r);
}

__global__ void prep_x3(const float* __restrict__ x0, const float* __restrict__ x1,
                        const float* __restrict__ x2,
                        const int* __restrict__ m0, const int* __restrict__ m1,
                        const int* __restrict__ m2) {
    __shared__ float s[32][33];
    const float* Xs[3] = {x0, x1, x2};
    const int* Ms[3] = {m0, m1, m2};
    int which = blockIdx.z >> 1, b = blockIdx.z & 1;
    const float* X = Xs[which];
    const int* mask = Ms[which];
    __half* XH = g_XH[which];
    __half* XL = g_XL[which];
    int t0 = blockIdx.x * 32, i0 = blockIdx.y * 32;
    int tx = threadIdx.x, ty = threadIdx.y;
#pragma unroll
    for (int rr = 0; rr < 4; rr++)
        s[ty + 8 * rr][tx] = X[((size_t)b * EM + i0 + ty + 8 * rr) * TT + t0 + tx];
    __syncthreads();
#pragma unroll
    for (int rr = 0; rr < 4; rr++) {
        int tl = ty + 8 * rr, t = t0 + tl;
        float x = s[tx][tl] * (float)mask[b * TT + t];
        __half h = __float2half_rn(x);
        size_t o = ((size_t)b * TT + t) * EM + i0 + tx;
        XH[o] = h;
        XL[o] = __float2half_rn(x - __half2float(h));
    }
}

__global__ void init_aux(const int* __restrict__ km) {
    __shared__ float red[8];
    int b = blockIdx.x, tid = threadIdx.x;
    for (int i = tid; i < NH * DH; i += 256) g_Sv[b * NH * DH + i] = 0.f;
    float c = 0.f;
    for (int t = tid; t < TT; t += 256) c += (float)km[b * TT + t];
    for (int o = 16; o; o >>= 1) c += __shfl_xor_sync(~0u, c, o);
    if ((tid & 31) == 0) red[tid >> 5] = c;
    __syncthreads();
    if (tid == 0) {
        float tt = 0.f;
        for (int w = 0; w < 8; w++) tt += red[w];
        g_nv[b] = tt;
    }
}

// ---------------- projection core (fp16 2-MMA, 4-stage cp.async ring) ----------------
// block tile 128m x 64t, K-chunk 32, one sync/chunk, 2 CTAs/SM.
// Stage: A[128]@0 (10240), Bh[64]@10240 (5120), Bl@15360 (5120); stage 20480 x 4.
#define PSTR 80
#define PSTG 20480
#define PSY_F 65
__device__ __forceinline__ void proj_core(
    const __half* __restrict__ gA0, const __half* __restrict__ gBh0,
    const __half* __restrict__ gBl0, const float* __restrict__ bias,
    const float* __restrict__ lng, const float* __restrict__ lnb,
    __half* __restrict__ oTD, __half* __restrict__ oDT,
    float* __restrict__ Yout, const int* __restrict__ km,
    int mode, int t0, int m0, int b, char* smc)
{
    uint32_t sb = smem_u32(smc);
    int tid = threadIdx.x, lane = tid & 31, wid = tid >> 5;
    int g = lane >> 2, tig = lane & 3;
    int wm = wid >> 1, wn = wid & 1;
    const __half* gA  = gA0 + (size_t)m0 * EM;
    const __half* gBh = gBh0 + ((size_t)b * TT + t0) * EM;
    const __half* gBl = gBl0 + ((size_t)b * TT + t0) * EM;

    auto issue = [&](int kc, int st) {
        int k0 = kc * 32;
        uint32_t base = sb + st * PSTG;
#pragma unroll
        for (int i = 0; i < 2; i++) {
            int idx = tid + i * 256;
            int r = idx >> 2, j = idx & 3;
            cpa16(base + (uint32_t)(r * PSTR + j * 16), gA + (size_t)r * EM + k0 + j * 8);
        }
        {
            int r = tid >> 2, j = tid & 3;
            uint32_t off = (uint32_t)(r * PSTR + j * 16);
            cpa16(base + 10240 + off, gBh + (size_t)r * EM + k0 + j * 8);
            cpa16(base + 15360 + off, gBl + (size_t)r * EM + k0 + j * 8);
        }
    };

    issue(0, 0); CP_COMMIT();
    issue(1, 1); CP_COMMIT();
    issue(2, 2); CP_COMMIT();

    float acc[2][4][4] = {};

    for (int kc = 0; kc < 16; kc++) {
        int st = kc & 3;
        CP_WAIT2();
        __syncthreads();
        uint32_t bA = sb + st * PSTG, bBh = bA + 10240, bBl = bA + 15360;
#pragma unroll
        for (int ks = 0; ks < 2; ks++) {
            uint32_t ah[2][4], bh[2][4], bl[2][4];
#pragma unroll
            for (int mf = 0; mf < 2; mf++)
                ldm_x4(ah[mf], sA_addr(bA, PSTR, wm * 32 + mf * 16, ks * 16, lane));
#pragma unroll
            for (int np = 0; np < 2; np++) {
                ldm_x4(bh[np], sB_addr(bBh, PSTR, wn * 32 + np * 16, ks * 16, lane));
                ldm_x4(bl[np], sB_addr(bBl, PSTR, wn * 32 + np * 16, ks * 16, lane));
            }
#pragma unroll
            for (int mf = 0; mf < 2; mf++)
#pragma unroll
                for (int nf = 0; nf < 4; nf++) {
                    mma16816(acc[mf][nf], ah[mf], &bh[nf >> 1][(nf & 1) * 2]);
                    mma16816(acc[mf][nf], ah[mf], &bl[nf >> 1][(nf & 1) * 2]);
                }
        }
        if (kc + 3 < 16) issue(kc + 3, (kc + 3) & 3);
        CP_COMMIT();
    }

    if (mode == 2) {
#pragma unroll
        for (int mf = 0; mf < 2; mf++)
#pragma unroll
            for (int rr = 0; rr < 2; rr++) {
                int m = m0 + wm * 32 + mf * 16 + g + rr * 8;
                float bi = bias[m];
                float* yo = Yout + ((size_t)b * EM + m) * TT + t0 + wn * 32;
#pragma unroll
                for (int nf = 0; nf < 4; nf++) {
                    float2 v = make_float2(acc[mf][nf][rr * 2] + bi, acc[mf][nf][rr * 2 + 1] + bi);
                    *(float2*)(yo + nf * 8 + 2 * tig) = v;
                }
            }
        return;
    }

    // ---- fused LN epilogue ----
    float* sY = (float*)smc;                       // [128][65] fp32
    float* sSvW = (float*)(smc + 128 * PSY_F * 4); // [4][64]
    __syncthreads();
#pragma unroll
    for (int mf = 0; mf < 2; mf++)
#pragma unroll
        for (int rr = 0; rr < 2; rr++) {
            int m = wm * 32 + mf * 16 + g + rr * 8;
            float bi = bias[m0 + m];
#pragma unroll
            for (int nf = 0; nf < 4; nf++) {
                int t = wn * 32 + nf * 8 + 2 * tig;
                sY[m * PSY_F + t] = acc[mf][nf][rr * 2] + bi;
                sY[m * PSY_F + t + 1] = acc[mf][nf][rr * 2 + 1] + bi;
            }
        }
    __syncthreads();

    if (tid < 128) {
        int hh = tid >> 6, tl = tid & 63;
        int t = t0 + tl;
        int h = (m0 >> 6) + hh;
        float v[64];
        float s = 0.f, s2 = 0.f;
#pragma unroll
        for (int d = 0; d < 64; d++) {
            v[d] = sY[(hh * 64 + d) * PSY_F + tl];
            s += v[d]; s2 += v[d] * v[d];
        }
        float mu = s * (1.f / 64), var = s2 * (1.f / 64) - mu * mu, rs = rsqrtf(var + EPS);
#pragma unroll
        for (int d = 0; d < 64; d++) v[d] = (v[d] - mu) * rs * lng[d] + lnb[d];

        if (mode == 0) {
            __half* o = oTD + (((size_t)b * NH + h) * TT + t) * 64;
#pragma unroll
            for (int dd = 0; dd < 64; dd += 8) {
                uint32_t pk[4];
#pragma unroll
                for (int e = 0; e < 4; e++) {
                    __half2 p = __floats2half2_rn(v[dd + 2 * e], v[dd + 2 * e + 1]);
                    pk[e] = *(uint32_t*)&p;
                }
                *(uint4*)(o + dd) = *(uint4*)pk;
            }
        } else {
            __half* o = oDT + ((size_t)b * NH + h) * (size_t)(64 * TT) + t;
#pragma unroll
            for (int d = 0; d < 64; d++) o[(size_t)d * TT] = __float2half_rn(v[d]);
            float w = (float)km[b * TT + t];
#pragma unroll
            for (int d = 0; d < 64; d++) {
                float x = v[d] * w;
                for (int off = 16; off; off >>= 1) x += __shfl_xor_sync(~0u, x, off);
                if (lane == 0) sSvW[wid * 64 + d] = x;
            }
        }
    }
    if (mode == 1) {
        __syncthreads();
        if (tid < 128) {
            int hh = tid >> 6, d = tid & 63;
            float val = sSvW[(hh * 2) * 64 + d] + sSvW[(hh * 2 + 1) * 64 + d];
            atomicAdd(&g_Sv[((size_t)b * NH + (m0 >> 6) + hh) * 64 + d], val);
        }
    }
}

// merged QKV projection: grid (TT/64, EM/128, 3*BB)
__global__ void __launch_bounds__(256, 2) qkv_kernel(
    const float* b0, const float* b1, const float* b2,
    const float* g0, const float* g1, const float* g2,
    const float* e0, const float* e1, const float* e2,
    const int* km)
{
    extern __shared__ __align__(16) char smc[];
    int which = blockIdx.z / BB, b = blockIdx.z % BB;
    const float* biases[3] = {b0, b1, b2};
    const float* lngs[3] = {g0, g1, g2};
    const float* lnbs[3] = {e0, e1, e2};
    __half* oTD = (which == 0) ? g_Qb : g_Kb;
    proj_core(g_WH[which], g_XH[which], g_XL[which],
              biases[which], lngs[which], lnbs[which],
              oTD, g_Vb, nullptr, km,
              (which == 2) ? 1 : 0, blockIdx.x * 64, blockIdx.y * 128, b, smc);
}

__global__ void __launch_bounds__(256, 2) outproj_kernel(const float* bias, float* out)
{
    extern __shared__ __align__(16) char smc[];
    proj_core(g_WH[3], g_AoH, g_AoL, bias, nullptr, nullptr,
              nullptr, nullptr, out, nullptr, 2,
              blockIdx.x * 64, blockIdx.y * 128, blockIdx.z, smc);
}

// ---------------- fused attention (cp.async 2-stage, register-resident U) ----------------
#define ASTG 35840
#define AQSZ 9216
#define AKMS 80896
__global__ void __launch_bounds__(128) attn_wmma(const int* __restrict__ qmask,
                                                 const int* __restrict__ kmask)
{
    extern __shared__ __align__(16) char smc[];
    uint32_t sb = smem_u32(smc);
    __half* sQ = (__half*)smc;
    uint32_t aQ = sb;
    int tid = threadIdx.x, lane = tid & 31, wid = tid >> 5;
    int g = lane >> 2, tig = lane & 3;
    int q0 = blockIdx.x * 64;
    int b = blockIdx.y >> 3, h = blockIdx.y & 7;
    size_t hb = (size_t)(b * NH + h);
    const __half* gQ = g_Qb + (hb * TT + q0) * 64;
    const __half* gK = g_Kb + hb * TT * 64;
    const __half* gV = g_Vb + hb * (size_t)(64 * TT);

    auto issue = [&](int kc, int st) {
        int k0 = kc * 128;
        uint32_t base = sb + AQSZ + st * ASTG;
#pragma unroll
        for (int i = 0; i < 8; i++) {
            int idx = tid + i * 128;
            int r = idx >> 3, j = idx & 7;
            cpa16(base + (uint32_t)(r * 72 + j * 8) * 2, gK + (size_t)(k0 + r) * 64 + j * 8);
        }
#pragma unroll
        for (int i = 0; i < 8; i++) {
            int idx = tid + i * 128;
            int r = idx >> 4, j = idx & 15;
            cpa16(base + 18432 + (uint32_t)(r * 136 + j * 8) * 2, gV + (size_t)r * TT + k0 + j * 8);
        }
        cpa4(sb + AKMS + st * 512 + tid * 4, kmask + b * TT + k0 + tid);
    };

    for (int idx = tid; idx < 512; idx += 128) {
        int r = idx >> 3, j = idx & 7;
        *(uint4*)(sQ + r * 72 + j * 8) = *(const uint4*)(gQ + (size_t)r * 64 + j * 8);
    }

    issue(0, 0); CP_COMMIT();
    issue(1, 1); CP_COMMIT();

    float oc[8][4] = {};
    float rs0 = 0.f, rs1 = 0.f;
    const float inv181 = 1.f / 181.f;

    for (int kc = 0; kc < 16; kc++) {
        int st = kc & 1;
        CP_WAIT1();
        __syncthreads();
        uint32_t aK = sb + AQSZ + st * ASTG, aV = aK + 18432;
        const int* kmsi = (const int*)(smc + AKMS + st * 512);

        float sc[16][4] = {};
#pragma unroll
        for (int ks = 0; ks < 4; ks++) {
            uint32_t aq[4];
            ldm_x4(aq, sA_addr(aQ, 144, wid * 16, ks * 16, lane));
#pragma unroll
            for (int nb = 0; nb < 8; nb++) {
                uint32_t bk[4];
                ldm_x4(bk, sB_addr(aK, 144, nb * 16, ks * 16, lane));
                mma16816(sc[2 * nb], aq, &bk[0]);
                mma16816(sc[2 * nb + 1], aq, &bk[2]);
            }
        }

        uint32_t ua[8][4];
#pragma unroll
        for (int nf = 0; nf < 16; nf++) {
            int c0 = nf * 8 + 2 * tig;
            float k0f = (float)kmsi[c0], k1f = (float)kmsi[c0 + 1];
            float u0 = expm1p(sc[nf][0] * inv181) * k0f;
            float u1 = expm1p(sc[nf][1] * inv181) * k1f;
            float u2 = expm1p(sc[nf][2] * inv181) * k0f;
            float u3 = expm1p(sc[nf][3] * inv181) * k1f;
            rs0 += u0 + u1;
            rs1 += u2 + u3;
            __half2 p01 = __floats2half2_rn(u0, u1);
            __half2 p23 = __floats2half2_rn(u2, u3);
            int kk = nf >> 1, hi = (nf & 1) * 2;
            ua[kk][hi] = *(uint32_t*)&p01;
            ua[kk][hi + 1] = *(uint32_t*)&p23;
        }

#pragma unroll
        for (int kk = 0; kk < 8; kk++) {
#pragma unroll
            for (int db = 0; db < 4; db++) {
                uint32_t bv[4];
                ldm_x4(bv, sB_addr(aV, 272, db * 16, kk * 16, lane));
                mma16816(oc[2 * db], ua[kk], &bv[0]);
                mma16816(oc[2 * db + 1], ua[kk], &bv[2]);
            }
        }
        __syncthreads();
        if (kc + 2 < 16) issue(kc + 2, st);
        CP_COMMIT();
    }

    rs0 += __shfl_xor_sync(~0u, rs0, 1);
    rs0 += __shfl_xor_sync(~0u, rs0, 2);
    rs1 += __shfl_xor_sync(~0u, rs1, 1);
    rs1 += __shfl_xor_sync(~0u, rs1, 2);

    float nv = g_nv[b];
    const float* sv = g_Sv + hb * 64;
#pragma unroll
    for (int rr = 0; rr < 2; rr++) {
        int row = wid * 16 + g + rr * 8;
        int q = q0 + row;
        float l = nv + (rr ? rs1 : rs0);
        float inv = (qmask[b * TT + q] != 0) ? (1.f / l) : 0.f;
        __half* oH = g_AoH + ((size_t)b * TT + q) * EM + h * 64;
        __half* oL = g_AoL + ((size_t)b * TT + q) * EM + h * 64;
#pragma unroll
        for (int df = 0; df < 8; df++) {
            int d0 = df * 8 + 2 * tig;
            float x0 = (oc[df][rr * 2] + sv[d0]) * inv;
            float x1 = (oc[df][rr * 2 + 1] + sv[d0 + 1]) * inv;
            __half h0 = __float2half_rn(x0), h1 = __float2half_rn(x1);
            __half2 ph = __halves2half2(h0, h1);
            __half2 pl = __floats2half2_rn(x0 - __half2float(h0), x1 - __half2float(h1));
            *(uint32_t*)(oH + d0) = *(uint32_t*)&ph;
            *(uint32_t*)(oL + d0) = *(uint32_t*)&pl;
        }
    }
}

// ---------------- launch ----------------
extern "C" void kernel_launch(void* const* d_in, const int* in_sizes, int n_in,
                              void* d_out, int out_size) {
    const float* q  = (const float*)d_in[0];
    const float* k  = (const float*)d_in[1];
    const float* v  = (const float*)d_in[2];
    const int* qm   = (const int*)d_in[3];
    const int* km   = (const int*)d_in[4];
    const int* vm   = (const int*)d_in[5];
    const float* W[4]  = {(const float*)d_in[6], (const float*)d_in[8], (const float*)d_in[10], (const float*)d_in[12]};
    const float* bi[4] = {(const float*)d_in[7], (const float*)d_in[9], (const float*)d_in[11], (const float*)d_in[13]};
    const float* lng[3] = {(const float*)d_in[14], (const float*)d_in[16], (const float*)d_in[18]};
    const float* lnb[3] = {(const float*)d_in[15], (const float*)d_in[17], (const float*)d_in[19]};
    float* out = (float*)d_out;

    const int PROJ_SMEM = 4 * PSTG + 1024;     // 82944
    const int ATTN_SMEM = AKMS + 2 * 512;      // 81920
    cudaFuncSetAttribute(qkv_kernel, cudaFuncAttributeMaxDynamicSharedMemorySize, PROJ_SMEM);
    cudaFuncSetAttribute(outproj_kernel, cudaFuncAttributeMaxDynamicSharedMemorySize, PROJ_SMEM);
    cudaFuncSetAttribute(attn_wmma, cudaFuncAttributeMaxDynamicSharedMemorySize, ATTN_SMEM);

    prep_w4<<<dim3(EM, 4), 128>>>(W[0], W[1], W[2], W[3]);
    prep_x3<<<dim3(TT / 32, EM / 32, 3 * BB), dim3(32, 8)>>>(q, k, v, qm, km, vm);
    init_aux<<<BB, 256>>>(km);

    qkv_kernel<<<dim3(TT / 64, EM / 128, 3 * BB), 256, PROJ_SMEM>>>(
        bi[0], bi[1], bi[2], lng[0], lng[1], lng[2], lnb[0], lnb[1], lnb[2], km);

    attn_wmma<<<dim3(TT / 64, BB * NH), 128, ATTN_SMEM>>>(qm, km);

    outproj_kernel<<<dim3(TT / 64, EM / 128, BB), 256, PROJ_SMEM>>>(bi[3], out);
}

// round 15
// speedup vs baseline: 1.8877x; 1.0195x over previous
#include <cuda_runtime.h>
#include <cuda_fp16.h>
#include <cstdint>

#define BB 2
#define EM 512
#define NH 8
#define DH 64
#define TT 2048
#define EPS 1e-5f

// ---------------- scratch ----------------
__device__ __align__(256) __half g_WH[4][EM * EM];
__device__ __align__(256) __half g_XH[3][BB * TT * EM];
__device__ __align__(256) __half g_XL[3][BB * TT * EM];
__device__ __align__(256) __half g_Qb[BB * NH * TT * DH];
__device__ __align__(256) __half g_Kb[BB * NH * TT * DH];
__device__ __align__(256) __half g_Vb[BB * NH * DH * TT];
__device__ __align__(256) __half g_AoH[BB * TT * EM];
__device__ __align__(256) __half g_AoL[BB * TT * EM];
__device__ float g_Sv[BB * NH * DH];
__device__ float g_nv[BB];

// ---------------- helpers ----------------
__device__ __forceinline__ uint32_t smem_u32(const void* p) {
    uint32_t a;
    asm("{ .reg .u64 t; cvta.to.shared.u64 t, %1; cvt.u32.u64 %0, t; }" : "=r"(a) : "l"(p));
    return a;
}
__device__ __forceinline__ void cpa16(uint32_t s, const void* g) {
    asm volatile("cp.async.cg.shared.global [%0], [%1], 16;" :: "r"(s), "l"(g));
}
__device__ __forceinline__ void cpa4(uint32_t s, const void* g) {
    asm volatile("cp.async.ca.shared.global [%0], [%1], 4;" :: "r"(s), "l"(g));
}
#define CP_COMMIT() asm volatile("cp.async.commit_group;" ::: "memory")
#define CP_WAIT1()  asm volatile("cp.async.wait_group 1;" ::: "memory")
#define CP_WAIT2()  asm volatile("cp.async.wait_group 2;" ::: "memory")

__device__ __forceinline__ void ldm_x4(uint32_t* r, uint32_t a) {
    asm volatile("ldmatrix.sync.aligned.m8n8.x4.shared.b16 {%0,%1,%2,%3}, [%4];"
                 : "=r"(r[0]), "=r"(r[1]), "=r"(r[2]), "=r"(r[3]) : "r"(a));
}

__device__ __forceinline__ void mma16816(float* c, const uint32_t* a, const uint32_t* b) {
    asm volatile(
        "mma.sync.aligned.m16n8k16.row.col.f32.f16.f16.f32 "
        "{%0,%1,%2,%3}, {%4,%5,%6,%7}, {%8,%9}, {%0,%1,%2,%3};"
        : "+f"(c[0]), "+f"(c[1]), "+f"(c[2]), "+f"(c[3])
        : "r"(a[0]), "r"(a[1]), "r"(a[2]), "r"(a[3]), "r"(b[0]), "r"(b[1]));
}

__device__ __forceinline__ uint32_t sA_addr(uint32_t base, int stride, int mo, int ko, int lane) {
    int j = lane >> 3, r = lane & 7;
    return base + (uint32_t)((mo + ((j & 1) << 3) + r) * stride + (ko + ((j >> 1) << 3)) * 2);
}
__device__ __forceinline__ uint32_t sB_addr(uint32_t base, int stride, int no, int ko, int lane) {
    int j = lane >> 3, r = lane & 7;
    return base + (uint32_t)((no + ((j >> 1) << 3) + r) * stride + (ko + ((j & 1) << 3)) * 2);
}

__device__ __forceinline__ float expm1p(float s) {
    float p = 1.f / 720.f;
    p = fmaf(p, s, 1.f / 120.f);
    p = fmaf(p, s, 1.f / 24.f);
    p = fmaf(p, s, 1.f / 6.f);
    p = fmaf(p, s, 0.5f);
    p = fmaf(p, s, 1.f);
    return p * s;
}

// ---------------- prep kernels ----------------
__global__ void __launch_bounds__(128) prep_w4(const float* __restrict__ W0,
                                               const float* __restrict__ W1,
                                               const float* __restrict__ W2,
                                               const float* __restrict__ W3) {
    __shared__ float red[8];
    const float* Ws[4] = {W0, W1, W2, W3};
    int i = blockIdx.y, row = blockIdx.x, tid = threadIdx.x;
    const float* wr = Ws[i] + (size_t)row * EM;
    __half* WH = g_WH[i];
    float s = 0.f, s2 = 0.f;
    for (int c = tid; c < EM; c += 128) { float v = wr[c]; s += v; s2 += v * v; }
    for (int o = 16; o; o >>= 1) { s += __shfl_xor_sync(~0u, s, o); s2 += __shfl_xor_sync(~0u, s2, o); }
    if ((tid & 31) == 0) { red[tid >> 5] = s; red[4 + (tid >> 5)] = s2; }
    __syncthreads();
    s = red[0] + red[1] + red[2] + red[3];
    s2 = red[4] + red[5] + red[6] + red[7];
    float mu = s * (1.f / EM), var = s2 * (1.f / EM) - mu * mu, r = rsqrtf(var + EPS);
    for (int c = tid; c < EM; c += 128)
        WH[(size_t)row * EM + c] = __float2half_rn((wr[c] - mu) * r);
}

__global__ void prep_x3(const float* __restrict__ x0, const float* __restrict__ x1,
                        const float* __restrict__ x2,
                        const int* __restrict__ m0, const int* __restrict__ m1,
                        const int* __restrict__ m2) {
    __shared__ float s[32][33];
    const float* Xs[3] = {x0, x1, x2};
    const int* Ms[3] = {m0, m1, m2};
    int which = blockIdx.z >> 1, b = blockIdx.z & 1;
    const float* X = Xs[which];
    const int* mask = Ms[which];
    __half* XH = g_XH[which];
    __half* XL = g_XL[which];
    int t0 = blockIdx.x * 32, i0 = blockIdx.y * 32;
    int tx = threadIdx.x, ty = threadIdx.y;
#pragma unroll
    for (int rr = 0; rr < 4; rr++)
        s[ty + 8 * rr][tx] = X[((size_t)b * EM + i0 + ty + 8 * rr) * TT + t0 + tx];
    __syncthreads();
#pragma unroll
    for (int rr = 0; rr < 4; rr++) {
        int tl = ty + 8 * rr, t = t0 + tl;
        float x = s[tx][tl] * (float)mask[b * TT + t];
        __half h = __float2half_rn(x);
        size_t o = ((size_t)b * TT + t) * EM + i0 + tx;
        XH[o] = h;
        XL[o] = __float2half_rn(x - __half2float(h));
    }
}

__global__ void init_aux(const int* __restrict__ km) {
    __shared__ float red[8];
    int b = blockIdx.x, tid = threadIdx.x;
    for (int i = tid; i < NH * DH; i += 256) g_Sv[b * NH * DH + i] = 0.f;
    float c = 0.f;
    for (int t = tid; t < TT; t += 256) c += (float)km[b * TT + t];
    for (int o = 16; o; o >>= 1) c += __shfl_xor_sync(~0u, c, o);
    if ((tid & 31) == 0) red[tid >> 5] = c;
    __syncthreads();
    if (tid == 0) {
        float tt = 0.f;
        for (int w = 0; w < 8; w++) tt += red[w];
        g_nv[b] = tt;
    }
}

// ---------------- projection core (fp16 2-MMA, 4-stage cp.async ring) ----------------
#define PSTR 80
#define PSTG 20480
#define PSY_F 65
__device__ __forceinline__ void proj_core(
    const __half* __restrict__ gA0, const __half* __restrict__ gBh0,
    const __half* __restrict__ gBl0, const float* __restrict__ bias,
    const float* __restrict__ lng, const float* __restrict__ lnb,
    __half* __restrict__ oTD, __half* __restrict__ oDT,
    float* __restrict__ Yout, const int* __restrict__ km,
    int mode, int t0, int m0, int b, char* smc)
{
    uint32_t sb = smem_u32(smc);
    int tid = threadIdx.x, lane = tid & 31, wid = tid >> 5;
    int g = lane >> 2, tig = lane & 3;
    int wm = wid >> 1, wn = wid & 1;
    const __half* gA  = gA0 + (size_t)m0 * EM;
    const __half* gBh = gBh0 + ((size_t)b * TT + t0) * EM;
    const __half* gBl = gBl0 + ((size_t)b * TT + t0) * EM;

    auto issue = [&](int kc, int st) {
        int k0 = kc * 32;
        uint32_t base = sb + st * PSTG;
#pragma unroll
        for (int i = 0; i < 2; i++) {
            int idx = tid + i * 256;
            int r = idx >> 2, j = idx & 3;
            cpa16(base + (uint32_t)(r * PSTR + j * 16), gA + (size_t)r * EM + k0 + j * 8);
        }
        {
            int r = tid >> 2, j = tid & 3;
            uint32_t off = (uint32_t)(r * PSTR + j * 16);
            cpa16(base + 10240 + off, gBh + (size_t)r * EM + k0 + j * 8);
            cpa16(base + 15360 + off, gBl + (size_t)r * EM + k0 + j * 8);
        }
    };

    issue(0, 0); CP_COMMIT();
    issue(1, 1); CP_COMMIT();
    issue(2, 2); CP_COMMIT();

    float acc[2][4][4] = {};

    for (int kc = 0; kc < 16; kc++) {
        int st = kc & 3;
        CP_WAIT2();
        __syncthreads();
        uint32_t bA = sb + st * PSTG, bBh = bA + 10240, bBl = bA + 15360;
#pragma unroll
        for (int ks = 0; ks < 2; ks++) {
            uint32_t ah[2][4], bh[2][4], bl[2][4];
#pragma unroll
            for (int mf = 0; mf < 2; mf++)
                ldm_x4(ah[mf], sA_addr(bA, PSTR, wm * 32 + mf * 16, ks * 16, lane));
#pragma unroll
            for (int np = 0; np < 2; np++) {
                ldm_x4(bh[np], sB_addr(bBh, PSTR, wn * 32 + np * 16, ks * 16, lane));
                ldm_x4(bl[np], sB_addr(bBl, PSTR, wn * 32 + np * 16, ks * 16, lane));
            }
#pragma unroll
            for (int mf = 0; mf < 2; mf++)
#pragma unroll
                for (int nf = 0; nf < 4; nf++) {
                    mma16816(acc[mf][nf], ah[mf], &bh[nf >> 1][(nf & 1) * 2]);
                    mma16816(acc[mf][nf], ah[mf], &bl[nf >> 1][(nf & 1) * 2]);
                }
        }
        if (kc + 3 < 16) issue(kc + 3, (kc + 3) & 3);
        CP_COMMIT();
    }

    if (mode == 2) {
#pragma unroll
        for (int mf = 0; mf < 2; mf++)
#pragma unroll
            for (int rr = 0; rr < 2; rr++) {
                int m = m0 + wm * 32 + mf * 16 + g + rr * 8;
                float bi = bias[m];
                float* yo = Yout + ((size_t)b * EM + m) * TT + t0 + wn * 32;
#pragma unroll
                for (int nf = 0; nf < 4; nf++) {
                    float2 v = make_float2(acc[mf][nf][rr * 2] + bi, acc[mf][nf][rr * 2 + 1] + bi);
                    *(float2*)(yo + nf * 8 + 2 * tig) = v;
                }
            }
        return;
    }

    // ---- fused LN epilogue ----
    float* sY = (float*)smc;                       // [128][65] fp32
    float* sSvW = (float*)(smc + 128 * PSY_F * 4); // [4][64]
    __syncthreads();
#pragma unroll
    for (int mf = 0; mf < 2; mf++)
#pragma unroll
        for (int rr = 0; rr < 2; rr++) {
            int m = wm * 32 + mf * 16 + g + rr * 8;
            float bi = bias[m0 + m];
#pragma unroll
            for (int nf = 0; nf < 4; nf++) {
                int t = wn * 32 + nf * 8 + 2 * tig;
                sY[m * PSY_F + t] = acc[mf][nf][rr * 2] + bi;
                sY[m * PSY_F + t + 1] = acc[mf][nf][rr * 2 + 1] + bi;
            }
        }
    __syncthreads();

    if (tid < 128) {
        int hh = tid >> 6, tl = tid & 63;
        int t = t0 + tl;
        int h = (m0 >> 6) + hh;
        float v[64];
        float s = 0.f, s2 = 0.f;
#pragma unroll
        for (int d = 0; d < 64; d++) {
            v[d] = sY[(hh * 64 + d) * PSY_F + tl];
            s += v[d]; s2 += v[d] * v[d];
        }
        float mu = s * (1.f / 64), var = s2 * (1.f / 64) - mu * mu, rs = rsqrtf(var + EPS);
#pragma unroll
        for (int d = 0; d < 64; d++) v[d] = (v[d] - mu) * rs * lng[d] + lnb[d];

        if (mode == 0) {
            __half* o = oTD + (((size_t)b * NH + h) * TT + t) * 64;
#pragma unroll
            for (int dd = 0; dd < 64; dd += 8) {
                uint32_t pk[4];
#pragma unroll
                for (int e = 0; e < 4; e++) {
                    __half2 p = __floats2half2_rn(v[dd + 2 * e], v[dd + 2 * e + 1]);
                    pk[e] = *(uint32_t*)&p;
                }
                *(uint4*)(o + dd) = *(uint4*)pk;
            }
        } else {
            __half* o = oDT + ((size_t)b * NH + h) * (size_t)(64 * TT) + t;
#pragma unroll
            for (int d = 0; d < 64; d++) o[(size_t)d * TT] = __float2half_rn(v[d]);
            float w = (float)km[b * TT + t];
#pragma unroll
            for (int d = 0; d < 64; d++) {
                float x = v[d] * w;
                for (int off = 16; off; off >>= 1) x += __shfl_xor_sync(~0u, x, off);
                if (lane == 0) sSvW[wid * 64 + d] = x;
            }
        }
    }
    if (mode == 1) {
        __syncthreads();
        if (tid < 128) {
            int hh = tid >> 6, d = tid & 63;
            float val = sSvW[(hh * 2) * 64 + d] + sSvW[(hh * 2 + 1) * 64 + d];
            atomicAdd(&g_Sv[((size_t)b * NH + (m0 >> 6) + hh) * 64 + d], val);
        }
    }
}

// merged QKV projection: grid (TT/64, EM/128, 3*BB)
__global__ void __launch_bounds__(256, 2) qkv_kernel(
    const float* b0, const float* b1, const float* b2,
    const float* g0, const float* g1, const float* g2,
    const float* e0, const float* e1, const float* e2,
    const int* km)
{
    extern __shared__ __align__(16) char smc[];
    int which = blockIdx.z / BB, b = blockIdx.z % BB;
    const float* biases[3] = {b0, b1, b2};
    const float* lngs[3] = {g0, g1, g2};
    const float* lnbs[3] = {e0, e1, e2};
    __half* oTD = (which == 0) ? g_Qb : g_Kb;
    proj_core(g_WH[which], g_XH[which], g_XL[which],
              biases[which], lngs[which], lnbs[which],
              oTD, g_Vb, nullptr, km,
              (which == 2) ? 1 : 0, blockIdx.x * 64, blockIdx.y * 128, b, smc);
}

__global__ void __launch_bounds__(256, 2) outproj_kernel(const float* bias, float* out)
{
    extern __shared__ __align__(16) char smc[];
    proj_core(g_WH[3], g_AoH, g_AoL, bias, nullptr, nullptr,
              nullptr, nullptr, out, nullptr, 2,
              blockIdx.x * 64, blockIdx.y * 128, blockIdx.z, smc);
}

// ---------------- fused attention (split-k, 8 warps, cp.async 2-stage) ----------------
// warp (qs = wid>>1, kh = wid&1): 16q stripe x kh-th 64-col half of each 128-k chunk.
#define ASTG 35840
#define AQSZ 9216
#define AKMS 80896
__global__ void __launch_bounds__(256, 2) attn_wmma(const int* __restrict__ qmask,
                                                    const int* __restrict__ kmask)
{
    extern __shared__ __align__(16) char smc[];
    uint32_t sb = smem_u32(smc);
    __half* sQ = (__half*)smc;
    uint32_t aQ = sb;
    int tid = threadIdx.x, lane = tid & 31, wid = tid >> 5;
    int g = lane >> 2, tig = lane & 3;
    int qs = wid >> 1, kh = wid & 1;
    int q0 = blockIdx.x * 64;
    int b = blockIdx.y >> 3, h = blockIdx.y & 7;
    size_t hb = (size_t)(b * NH + h);
    const __half* gQ = g_Qb + (hb * TT + q0) * 64;
    const __half* gK = g_Kb + hb * TT * 64;
    const __half* gV = g_Vb + hb * (size_t)(64 * TT);

    auto issue = [&](int kc, int st) {
        int k0 = kc * 128;
        uint32_t base = sb + AQSZ + st * ASTG;
#pragma unroll
        for (int i = 0; i < 4; i++) {
            int idx = tid + i * 256;
            int r = idx >> 3, j = idx & 7;
            cpa16(base + (uint32_t)(r * 72 + j * 8) * 2, gK + (size_t)(k0 + r) * 64 + j * 8);
        }
#pragma unroll
        for (int i = 0; i < 4; i++) {
            int idx = tid + i * 256;
            int r = idx >> 4, j = idx & 15;
            cpa16(base + 18432 + (uint32_t)(r * 136 + j * 8) * 2, gV + (size_t)r * TT + k0 + j * 8);
        }
        if (tid < 128) cpa4(sb + AKMS + st * 512 + tid * 4, kmask + b * TT + k0 + tid);
    };

    for (int idx = tid; idx < 512; idx += 256) {
        int r = idx >> 3, j = idx & 7;
        *(uint4*)(sQ + r * 72 + j * 8) = *(const uint4*)(gQ + (size_t)r * 64 + j * 8);
    }

    issue(0, 0); CP_COMMIT();
    issue(1, 1); CP_COMMIT();

    float oc[8][4] = {};
    float rs0 = 0.f, rs1 = 0.f;
    const float inv181 = 1.f / 181.f;

    for (int kc = 0; kc < 16; kc++) {
        int st = kc & 1;
        CP_WAIT1();
        __syncthreads();
        uint32_t aK = sb + AQSZ + st * ASTG, aV = aK + 18432;
        const int* kmsi = (const int*)(smc + AKMS + st * 512);

        // S = Q @ K^T : 16q x 64k per warp (kh half)
        float sc[8][4] = {};
#pragma unroll
        for (int ks = 0; ks < 4; ks++) {
            uint32_t aq[4];
            ldm_x4(aq, sA_addr(aQ, 144, qs * 16, ks * 16, lane));
#pragma unroll
            for (int nb = 0; nb < 4; nb++) {
                uint32_t bk[4];
                ldm_x4(bk, sB_addr(aK, 144, kh * 64 + nb * 16, ks * 16, lane));
                mma16816(sc[2 * nb], aq, &bk[0]);
                mma16816(sc[2 * nb + 1], aq, &bk[2]);
            }
        }

        // convert S -> U A-fragments in registers
        uint32_t ua[4][4];
#pragma unroll
        for (int nf = 0; nf < 8; nf++) {
            int c0 = kh * 64 + nf * 8 + 2 * tig;
            float k0f = (float)kmsi[c0], k1f = (float)kmsi[c0 + 1];
            float u0 = expm1p(sc[nf][0] * inv181) * k0f;
            float u1 = expm1p(sc[nf][1] * inv181) * k1f;
            float u2 = expm1p(sc[nf][2] * inv181) * k0f;
            float u3 = expm1p(sc[nf][3] * inv181) * k1f;
            rs0 += u0 + u1;
            rs1 += u2 + u3;
            __half2 p01 = __floats2half2_rn(u0, u1);
            __half2 p23 = __floats2half2_rn(u2, u3);
            int kk = nf >> 1, hi = (nf & 1) * 2;
            ua[kk][hi] = *(uint32_t*)&p01;
            ua[kk][hi + 1] = *(uint32_t*)&p23;
        }

        // O += U @ V^T : 16q x 64d over this warp's 64 k
#pragma unroll
        for (int kk = 0; kk < 4; kk++) {
#pragma unroll
            for (int db = 0; db < 4; db++) {
                uint32_t bv[4];
                ldm_x4(bv, sB_addr(aV, 272, db * 16, kh * 64 + kk * 16, lane));
                mma16816(oc[2 * db], ua[kk], &bv[0]);
                mma16816(oc[2 * db + 1], ua[kk], &bv[2]);
            }
        }
        __syncthreads();
        if (kc + 2 < 16) issue(kc + 2, st);
        CP_COMMIT();
    }

    // quad-reduce rowsums within warp (each warp covered only its 64-col halves)
    rs0 += __shfl_xor_sync(~0u, rs0, 1);
    rs0 += __shfl_xor_sync(~0u, rs0, 2);
    rs1 += __shfl_xor_sync(~0u, rs1, 1);
    rs1 += __shfl_xor_sync(~0u, rs1, 2);

    // combine k-halves: kh=1 stages partials, kh=0 adds
    float* red = (float*)(smc + AQSZ);
    if (kh == 1) {
        float* r = &red[(qs * 32 + lane) * 34];
#pragma unroll
        for (int df = 0; df < 8; df++)
#pragma unroll
            for (int e = 0; e < 4; e++) r[df * 4 + e] = oc[df][e];
        r[32] = rs0; r[33] = rs1;
    }
    __syncthreads();
    if (kh == 0) {
        float* r = &red[(qs * 32 + lane) * 34];
#pragma unroll
        for (int df = 0; df < 8; df++)
#pragma unroll
            for (int e = 0; e < 4; e++) oc[df][e] += r[df * 4 + e];
        rs0 += r[32]; rs1 += r[33];

        float nv = g_nv[b];
        const float* sv = g_Sv + hb * 64;
#pragma unroll
        for (int rr = 0; rr < 2; rr++) {
            int row = qs * 16 + g + rr * 8;
            int q = q0 + row;
            float l = nv + (rr ? rs1 : rs0);
            float inv = (qmask[b * TT + q] != 0) ? (1.f / l) : 0.f;
            __half* oH = g_AoH + ((size_t)b * TT + q) * EM + h * 64;
            __half* oL = g_AoL + ((size_t)b * TT + q) * EM + h * 64;
#pragma unroll
            for (int df = 0; df < 8; df++) {
                int d0 = df * 8 + 2 * tig;
                float x0 = (oc[df][rr * 2] + sv[d0]) * inv;
                float x1 = (oc[df][rr * 2 + 1] + sv[d0 + 1]) * inv;
                __half h0 = __float2half_rn(x0), h1 = __float2half_rn(x1);
                __half2 ph = __halves2half2(h0, h1);
                __half2 pl = __floats2half2_rn(x0 - __half2float(h0), x1 - __half2float(h1));
                *(uint32_t*)(oH + d0) = *(uint32_t*)&ph;
                *(uint32_t*)(oL + d0) = *(uint32_t*)&pl;
            }
        }
    }
}

// ---------------- launch ----------------
extern "C" void kernel_launch(void* const* d_in, const int* in_sizes, int n_in,
                              void* d_out, int out_size) {
    const float* q  = (const float*)d_in[0];
    const float* k  = (const float*)d_in[1];
    const float* v  = (const float*)d_in[2];
    const int* qm   = (const int*)d_in[3];
    const int* km   = (const int*)d_in[4];
    const int* vm   = (const int*)d_in[5];
    const float* W[4]  = {(const float*)d_in[6], (const float*)d_in[8], (const float*)d_in[10], (const float*)d_in[12]};
    const float* bi[4] = {(const float*)d_in[7], (const float*)d_in[9], (const float*)d_in[11], (const float*)d_in[13]};
    const float* lng[3] = {(const float*)d_in[14], (const float*)d_in[16], (const float*)d_in[18]};
    const float* lnb[3] = {(const float*)d_in[15], (const float*)d_in[17], (const float*)d_in[19]};
    float* out = (float*)d_out;

    const int PROJ_SMEM = 4 * PSTG + 1024;     // 82944
    const int ATTN_SMEM = AKMS + 2 * 512;      // 81920
    cudaFuncSetAttribute(qkv_kernel, cudaFuncAttributeMaxDynamicSharedMemorySize, PROJ_SMEM);
    cudaFuncSetAttribute(outproj_kernel, cudaFuncAttributeMaxDynamicSharedMemorySize, PROJ_SMEM);
    cudaFuncSetAttribute(attn_wmma, cudaFuncAttributeMaxDynamicSharedMemorySize, ATTN_SMEM);

    prep_w4<<<dim3(EM, 4), 128>>>(W[0], W[1], W[2], W[3]);
    prep_x3<<<dim3(TT / 32, EM / 32, 3 * BB), dim3(32, 8)>>>(q, k, v, qm, km, vm);
    init_aux<<<BB, 256>>>(km);

    qkv_kernel<<<dim3(TT / 64, EM / 128, 3 * BB), 256, PROJ_SMEM>>>(
        bi[0], bi[1], bi[2], lng[0], lng[1], lng[2], lnb[0], lnb[1], lnb[2], km);

    attn_wmma<<<dim3(TT / 64, BB * NH), 256, ATTN_SMEM>>>(qm, km);

    outproj_kernel<<<dim3(TT / 64, EM / 128, BB), 256, PROJ_SMEM>>>(bi[3], out);
}

// round 16
// speedup vs baseline: 1.9467x; 1.0313x over previous
#include <cuda_runtime.h>
#include <cuda_fp16.h>
#include <cstdint>

#define BB 2
#define EM 512
#define NH 8
#define DH 64
#define TT 2048
#define EPS 1e-5f

// ---------------- scratch ----------------
__device__ __align__(256) __half g_WH[4][EM * EM];
__device__ __align__(256) __half g_XH[3][BB * TT * EM];
__device__ __align__(256) __half g_XL[3][BB * TT * EM];
__device__ __align__(256) __half g_Qb[BB * NH * TT * DH];
__device__ __align__(256) __half g_Kb[BB * NH * TT * DH];
__device__ __align__(256) __half g_Vb[BB * NH * DH * TT];
__device__ __align__(256) __half g_AoH[BB * TT * EM];
__device__ __align__(256) __half g_AoL[BB * TT * EM];
__device__ float g_Sv[BB * NH * DH];
__device__ float g_nv[BB];

// ---------------- helpers ----------------
__device__ __forceinline__ uint32_t smem_u32(const void* p) {
    uint32_t a;
    asm("{ .reg .u64 t; cvta.to.shared.u64 t, %1; cvt.u32.u64 %0, t; }" : "=r"(a) : "l"(p));
    return a;
}
__device__ __forceinline__ void cpa16(uint32_t s, const void* g) {
    asm volatile("cp.async.cg.shared.global [%0], [%1], 16;" :: "r"(s), "l"(g));
}
__device__ __forceinline__ void cpa4(uint32_t s, const void* g) {
    asm volatile("cp.async.ca.shared.global [%0], [%1], 4;" :: "r"(s), "l"(g));
}
#define CP_COMMIT() asm volatile("cp.async.commit_group;" ::: "memory")
#define CP_WAIT1()  asm volatile("cp.async.wait_group 1;" ::: "memory")

__device__ __forceinline__ void ldm_x4(uint32_t* r, uint32_t a) {
    asm volatile("ldmatrix.sync.aligned.m8n8.x4.shared.b16 {%0,%1,%2,%3}, [%4];"
                 : "=r"(r[0]), "=r"(r[1]), "=r"(r[2]), "=r"(r[3]) : "r"(a));
}

__device__ __forceinline__ void mma16816(float* c, const uint32_t* a, const uint32_t* b) {
    asm volatile(
        "mma.sync.aligned.m16n8k16.row.col.f32.f16.f16.f32 "
        "{%0,%1,%2,%3}, {%4,%5,%6,%7}, {%8,%9}, {%0,%1,%2,%3};"
        : "+f"(c[0]), "+f"(c[1]), "+f"(c[2]), "+f"(c[3])
        : "r"(a[0]), "r"(a[1]), "r"(a[2]), "r"(a[3]), "r"(b[0]), "r"(b[1]));
}

__device__ __forceinline__ uint32_t sA_addr(uint32_t base, int stride, int mo, int ko, int lane) {
    int j = lane >> 3, r = lane & 7;
    return base + (uint32_t)((mo + ((j & 1) << 3) + r) * stride + (ko + ((j >> 1) << 3)) * 2);
}
__device__ __forceinline__ uint32_t sB_addr(uint32_t base, int stride, int no, int ko, int lane) {
    int j = lane >> 3, r = lane & 7;
    return base + (uint32_t)((no + ((j >> 1) << 3) + r) * stride + (ko + ((j & 1) << 3)) * 2);
}

__device__ __forceinline__ float expm1p(float s) {
    float p = 1.f / 720.f;
    p = fmaf(p, s, 1.f / 120.f);
    p = fmaf(p, s, 1.f / 24.f);
    p = fmaf(p, s, 1.f / 6.f);
    p = fmaf(p, s, 0.5f);
    p = fmaf(p, s, 1.f);
    return p * s;
}

// ---------------- prep kernels ----------------
__global__ void __launch_bounds__(128) prep_w4(const float* __restrict__ W0,
                                               const float* __restrict__ W1,
                                               const float* __restrict__ W2,
                                               const float* __restrict__ W3) {
    __shared__ float red[8];
    const float* Ws[4] = {W0, W1, W2, W3};
    int i = blockIdx.y, row = blockIdx.x, tid = threadIdx.x;
    const float* wr = Ws[i] + (size_t)row * EM;
    __half* WH = g_WH[i];
    float s = 0.f, s2 = 0.f;
    for (int c = tid; c < EM; c += 128) { float v = wr[c]; s += v; s2 += v * v; }
    for (int o = 16; o; o >>= 1) { s += __shfl_xor_sync(~0u, s, o); s2 += __shfl_xor_sync(~0u, s2, o); }
    if ((tid & 31) == 0) { red[tid >> 5] = s; red[4 + (tid >> 5)] = s2; }
    __syncthreads();
    s = red[0] + red[1] + red[2] + red[3];
    s2 = red[4] + red[5] + red[6] + red[7];
    float mu = s * (1.f / EM), var = s2 * (1.f / EM) - mu * mu, r = rsqrtf(var + EPS);
    for (int c = tid; c < EM; c += 128)
        WH[(size_t)row * EM + c] = __float2half_rn((wr[c] - mu) * r);
}

__global__ void prep_x3(const float* __restrict__ x0, const float* __restrict__ x1,
                        const float* __restrict__ x2,
                        const int* __restrict__ m0, const int* __restrict__ m1,
                        const int* __restrict__ m2) {
    __shared__ float s[32][33];
    const float* Xs[3] = {x0, x1, x2};
    const int* Ms[3] = {m0, m1, m2};
    int which = blockIdx.z >> 1, b = blockIdx.z & 1;
    const float* X = Xs[which];
    const int* mask = Ms[which];
    __half* XH = g_XH[which];
    __half* XL = g_XL[which];
    int t0 = blockIdx.x * 32, i0 = blockIdx.y * 32;
    int tx = threadIdx.x, ty = threadIdx.y;
#pragma unroll
    for (int rr = 0; rr < 4; rr++)
        s[ty + 8 * rr][tx] = X[((size_t)b * EM + i0 + ty + 8 * rr) * TT + t0 + tx];
    __syncthreads();
#pragma unroll
    for (int rr = 0; rr < 4; rr++) {
        int tl = ty + 8 * rr, t = t0 + tl;
        float x = s[tx][tl] * (float)mask[b * TT + t];
        __half h = __float2half_rn(x);
        size_t o = ((size_t)b * TT + t) * EM + i0 + tx;
        XH[o] = h;
        XL[o] = __float2half_rn(x - __half2float(h));
    }
}

__global__ void init_aux(const int* __restrict__ km) {
    __shared__ float red[8];
    int b = blockIdx.x, tid = threadIdx.x;
    for (int i = tid; i < NH * DH; i += 256) g_Sv[b * NH * DH + i] = 0.f;
    float c = 0.f;
    for (int t = tid; t < TT; t += 256) c += (float)km[b * TT + t];
    for (int o = 16; o; o >>= 1) c += __shfl_xor_sync(~0u, c, o);
    if ((tid & 31) == 0) red[tid >> 5] = c;
    __syncthreads();
    if (tid == 0) {
        float tt = 0.f;
        for (int w = 0; w < 8; w++) tt += red[w];
        g_nv[b] = tt;
    }
}

// ---------------- projection core (fp16 2-MMA, K-chunk 64, 3-stage ring) ----------------
// block tile 128m x 64t, ONE sync per 64-k chunk (8 barriers), 2 CTAs/SM.
// Stage (stride 144B): A[128]@0 (18432), Bh[64]@18432 (9216), Bl@27648 (9216); 36864 x 3.
#define PSTR 144
#define PSTG 36864
#define PSY_F 65
__device__ __forceinline__ void proj_core(
    const __half* __restrict__ gA0, const __half* __restrict__ gBh0,
    const __half* __restrict__ gBl0, const float* __restrict__ bias,
    const float* __restrict__ lng, const float* __restrict__ lnb,
    __half* __restrict__ oTD, __half* __restrict__ oDT,
    float* __restrict__ Yout, const int* __restrict__ km,
    int mode, int t0, int m0, int b, char* smc)
{
    uint32_t sb = smem_u32(smc);
    int tid = threadIdx.x, lane = tid & 31, wid = tid >> 5;
    int g = lane >> 2, tig = lane & 3;
    int wm = wid >> 1, wn = wid & 1;
    const __half* gA  = gA0 + (size_t)m0 * EM;
    const __half* gBh = gBh0 + ((size_t)b * TT + t0) * EM;
    const __half* gBl = gBl0 + ((size_t)b * TT + t0) * EM;

    auto issue = [&](int kc, int st) {
        int k0 = kc * 64;
        uint32_t base = sb + st * PSTG;
#pragma unroll
        for (int i = 0; i < 4; i++) {
            int idx = tid + i * 256;
            int r = idx >> 3, j = idx & 7;
            cpa16(base + (uint32_t)(r * PSTR + j * 16), gA + (size_t)r * EM + k0 + j * 8);
        }
#pragma unroll
        for (int i = 0; i < 2; i++) {
            int idx = tid + i * 256;
            int r = idx >> 3, j = idx & 7;
            uint32_t off = (uint32_t)(r * PSTR + j * 16);
            cpa16(base + 18432 + off, gBh + (size_t)r * EM + k0 + j * 8);
            cpa16(base + 27648 + off, gBl + (size_t)r * EM + k0 + j * 8);
        }
    };

    issue(0, 0); CP_COMMIT();
    issue(1, 1); CP_COMMIT();

    float acc[2][4][4] = {};

    for (int kc = 0; kc < 8; kc++) {
        int st = kc % 3;
        CP_WAIT1();
        __syncthreads();
        uint32_t bA = sb + st * PSTG, bBh = bA + 18432, bBl = bA + 27648;
#pragma unroll
        for (int ks = 0; ks < 4; ks++) {
            uint32_t ah[2][4], bh[2][4], bl[2][4];
#pragma unroll
            for (int mf = 0; mf < 2; mf++)
                ldm_x4(ah[mf], sA_addr(bA, PSTR, wm * 32 + mf * 16, ks * 16, lane));
#pragma unroll
            for (int np = 0; np < 2; np++) {
                ldm_x4(bh[np], sB_addr(bBh, PSTR, wn * 32 + np * 16, ks * 16, lane));
                ldm_x4(bl[np], sB_addr(bBl, PSTR, wn * 32 + np * 16, ks * 16, lane));
            }
#pragma unroll
            for (int mf = 0; mf < 2; mf++)
#pragma unroll
                for (int nf = 0; nf < 4; nf++) {
                    mma16816(acc[mf][nf], ah[mf], &bh[nf >> 1][(nf & 1) * 2]);
                    mma16816(acc[mf][nf], ah[mf], &bl[nf >> 1][(nf & 1) * 2]);
                }
        }
        if (kc + 2 < 8) issue(kc + 2, (kc + 2) % 3);
        CP_COMMIT();
    }

    if (mode == 2) {
#pragma unroll
        for (int mf = 0; mf < 2; mf++)
#pragma unroll
            for (int rr = 0; rr < 2; rr++) {
                int m = m0 + wm * 32 + mf * 16 + g + rr * 8;
                float bi = bias[m];
                float* yo = Yout + ((size_t)b * EM + m) * TT + t0 + wn * 32;
#pragma unroll
                for (int nf = 0; nf < 4; nf++) {
                    float2 v = make_float2(acc[mf][nf][rr * 2] + bi, acc[mf][nf][rr * 2 + 1] + bi);
                    *(float2*)(yo + nf * 8 + 2 * tig) = v;
                }
            }
        return;
    }

    // ---- fused LN epilogue ----
    float* sY = (float*)smc;                       // [128][65] fp32
    float* sSvW = (float*)(smc + 128 * PSY_F * 4); // [4][64]
    __syncthreads();
#pragma unroll
    for (int mf = 0; mf < 2; mf++)
#pragma unroll
        for (int rr = 0; rr < 2; rr++) {
            int m = wm * 32 + mf * 16 + g + rr * 8;
            float bi = bias[m0 + m];
#pragma unroll
            for (int nf = 0; nf < 4; nf++) {
                int t = wn * 32 + nf * 8 + 2 * tig;
                sY[m * PSY_F + t] = acc[mf][nf][rr * 2] + bi;
                sY[m * PSY_F + t + 1] = acc[mf][nf][rr * 2 + 1] + bi;
            }
        }
    __syncthreads();

    if (tid < 128) {
        int hh = tid >> 6, tl = tid & 63;
        int t = t0 + tl;
        int h = (m0 >> 6) + hh;
        float v[64];
        float s = 0.f, s2 = 0.f;
#pragma unroll
        for (int d = 0; d < 64; d++) {
            v[d] = sY[(hh * 64 + d) * PSY_F + tl];
            s += v[d]; s2 += v[d] * v[d];
        }
        float mu = s * (1.f / 64), var = s2 * (1.f / 64) - mu * mu, rs = rsqrtf(var + EPS);
#pragma unroll
        for (int d = 0; d < 64; d++) v[d] = (v[d] - mu) * rs * lng[d] + lnb[d];

        if (mode == 0) {
            __half* o = oTD + (((size_t)b * NH + h) * TT + t) * 64;
#pragma unroll
            for (int dd = 0; dd < 64; dd += 8) {
                uint32_t pk[4];
#pragma unroll
                for (int e = 0; e < 4; e++) {
                    __half2 p = __floats2half2_rn(v[dd + 2 * e], v[dd + 2 * e + 1]);
                    pk[e] = *(uint32_t*)&p;
                }
                *(uint4*)(o + dd) = *(uint4*)pk;
            }
        } else {
            __half* o = oDT + ((size_t)b * NH + h) * (size_t)(64 * TT) + t;
#pragma unroll
            for (int d = 0; d < 64; d++) o[(size_t)d * TT] = __float2half_rn(v[d]);
            float w = (float)km[b * TT + t];
#pragma unroll
            for (int d = 0; d < 64; d++) {
                float x = v[d] * w;
                for (int off = 16; off; off >>= 1) x += __shfl_xor_sync(~0u, x, off);
                if (lane == 0) sSvW[wid * 64 + d] = x;
            }
        }
    }
    if (mode == 1) {
        __syncthreads();
        if (tid < 128) {
            int hh = tid >> 6, d = tid & 63;
            float val = sSvW[(hh * 2) * 64 + d] + sSvW[(hh * 2 + 1) * 64 + d];
            atomicAdd(&g_Sv[((size_t)b * NH + (m0 >> 6) + hh) * 64 + d], val);
        }
    }
}

// merged QKV projection: grid (TT/64, EM/128, 3*BB)
__global__ void __launch_bounds__(256, 2) qkv_kernel(
    const float* b0, const float* b1, const float* b2,
    const float* g0, const float* g1, const float* g2,
    const float* e0, const float* e1, const float* e2,
    const int* km)
{
    extern __shared__ __align__(16) char smc[];
    int which = blockIdx.z / BB, b = blockIdx.z % BB;
    const float* biases[3] = {b0, b1, b2};
    const float* lngs[3] = {g0, g1, g2};
    const float* lnbs[3] = {e0, e1, e2};
    __half* oTD = (which == 0) ? g_Qb : g_Kb;
    proj_core(g_WH[which], g_XH[which], g_XL[which],
              biases[which], lngs[which], lnbs[which],
              oTD, g_Vb, nullptr, km,
              (which == 2) ? 1 : 0, blockIdx.x * 64, blockIdx.y * 128, b, smc);
}

__global__ void __launch_bounds__(256, 2) outproj_kernel(const float* bias, float* out)
{
    extern __shared__ __align__(16) char smc[];
    proj_core(g_WH[3], g_AoH, g_AoL, bias, nullptr, nullptr,
              nullptr, nullptr, out, nullptr, 2,
              blockIdx.x * 64, blockIdx.y * 128, blockIdx.z, smc);
}

// ---------------- fused attention (split-k, 8 warps, cp.async 2-stage) ----------------
#define ASTG 35840
#define AQSZ 9216
#define AKMS 80896
__global__ void __launch_bounds__(256, 2) attn_wmma(const int* __restrict__ qmask,
                                                    const int* __restrict__ kmask)
{
    extern __shared__ __align__(16) char smc[];
    uint32_t sb = smem_u32(smc);
    __half* sQ = (__half*)smc;
    uint32_t aQ = sb;
    int tid = threadIdx.x, lane = tid & 31, wid = tid >> 5;
    int g = lane >> 2, tig = lane & 3;
    int qs = wid >> 1, kh = wid & 1;
    int q0 = blockIdx.x * 64;
    int b = blockIdx.y >> 3, h = blockIdx.y & 7;
    size_t hb = (size_t)(b * NH + h);
    const __half* gQ = g_Qb + (hb * TT + q0) * 64;
    const __half* gK = g_Kb + hb * TT * 64;
    const __half* gV = g_Vb + hb * (size_t)(64 * TT);

    auto issue = [&](int kc, int st) {
        int k0 = kc * 128;
        uint32_t base = sb + AQSZ + st * ASTG;
#pragma unroll
        for (int i = 0; i < 4; i++) {
            int idx = tid + i * 256;
            int r = idx >> 3, j = idx & 7;
            cpa16(base + (uint32_t)(r * 72 + j * 8) * 2, gK + (size_t)(k0 + r) * 64 + j * 8);
        }
#pragma unroll
        for (int i = 0; i < 4; i++) {
            int idx = tid + i * 256;
            int r = idx >> 4, j = idx & 15;
            cpa16(base + 18432 + (uint32_t)(r * 136 + j * 8) * 2, gV + (size_t)r * TT + k0 + j * 8);
        }
        if (tid < 128) cpa4(sb + AKMS + st * 512 + tid * 4, kmask + b * TT + k0 + tid);
    };

    for (int idx = tid; idx < 512; idx += 256) {
        int r = idx >> 3, j = idx & 7;
        *(uint4*)(sQ + r * 72 + j * 8) = *(const uint4*)(gQ + (size_t)r * 64 + j * 8);
    }

    issue(0, 0); CP_COMMIT();
    issue(1, 1); CP_COMMIT();

    float oc[8][4] = {};
    float rs0 = 0.f, rs1 = 0.f;
    const float inv181 = 1.f / 181.f;

    for (int kc = 0; kc < 16; kc++) {
        int st = kc & 1;
        CP_WAIT1();
        __syncthreads();
        uint32_t aK = sb + AQSZ + st * ASTG, aV = aK + 18432;
        const int* kmsi = (const int*)(smc + AKMS + st * 512);

        float sc[8][4] = {};
#pragma unroll
        for (int ks = 0; ks < 4; ks++) {
            uint32_t aq[4];
            ldm_x4(aq, sA_addr(aQ, 144, qs * 16, ks * 16, lane));
#pragma unroll
            for (int nb = 0; nb < 4; nb++) {
                uint32_t bk[4];
                ldm_x4(bk, sB_addr(aK, 144, kh * 64 + nb * 16, ks * 16, lane));
                mma16816(sc[2 * nb], aq, &bk[0]);
                mma16816(sc[2 * nb + 1], aq, &bk[2]);
            }
        }

        uint32_t ua[4][4];
#pragma unroll
        for (int nf = 0; nf < 8; nf++) {
            int c0 = kh * 64 + nf * 8 + 2 * tig;
            float k0f = (float)kmsi[c0], k1f = (float)kmsi[c0 + 1];
            float u0 = expm1p(sc[nf][0] * inv181) * k0f;
            float u1 = expm1p(sc[nf][1] * inv181) * k1f;
            float u2 = expm1p(sc[nf][2] * inv181) * k0f;
            float u3 = expm1p(sc[nf][3] * inv181) * k1f;
            rs0 += u0 + u1;
            rs1 += u2 + u3;
            __half2 p01 = __floats2half2_rn(u0, u1);
            __half2 p23 = __floats2half2_rn(u2, u3);
            int kk = nf >> 1, hi = (nf & 1) * 2;
            ua[kk][hi] = *(uint32_t*)&p01;
            ua[kk][hi + 1] = *(uint32_t*)&p23;
        }

#pragma unroll
        for (int kk = 0; kk < 4; kk++) {
#pragma unroll
            for (int db = 0; db < 4; db++) {
                uint32_t bv[4];
                ldm_x4(bv, sB_addr(aV, 272, db * 16, kh * 64 + kk * 16, lane));
                mma16816(oc[2 * db], ua[kk], &bv[0]);
                mma16816(oc[2 * db + 1], ua[kk], &bv[2]);
            }
        }
        __syncthreads();
        if (kc + 2 < 16) issue(kc + 2, st);
        CP_COMMIT();
    }

    rs0 += __shfl_xor_sync(~0u, rs0, 1);
    rs0 += __shfl_xor_sync(~0u, rs0, 2);
    rs1 += __shfl_xor_sync(~0u, rs1, 1);
    rs1 += __shfl_xor_sync(~0u, rs1, 2);

    float* red = (float*)(smc + AQSZ);
    if (kh == 1) {
        float* r = &red[(qs * 32 + lane) * 34];
#pragma unroll
        for (int df = 0; df < 8; df++)
#pragma unroll
            for (int e = 0; e < 4; e++) r[df * 4 + e] = oc[df][e];
        r[32] = rs0; r[33] = rs1;
    }
    __syncthreads();
    if (kh == 0) {
        float* r = &red[(qs * 32 + lane) * 34];
#pragma unroll
        for (int df = 0; df < 8; df++)
#pragma unroll
            for (int e = 0; e < 4; e++) oc[df][e] += r[df * 4 + e];
        rs0 += r[32]; rs1 += r[33];

        float nv = g_nv[b];
        const float* sv = g_Sv + hb * 64;
#pragma unroll
        for (int rr = 0; rr < 2; rr++) {
            int row = qs * 16 + g + rr * 8;
            int q = q0 + row;
            float l = nv + (rr ? rs1 : rs0);
            float inv = (qmask[b * TT + q] != 0) ? (1.f / l) : 0.f;
            __half* oH = g_AoH + ((size_t)b * TT + q) * EM + h * 64;
            __half* oL = g_AoL + ((size_t)b * TT + q) * EM + h * 64;
#pragma unroll
            for (int df = 0; df < 8; df++) {
                int d0 = df * 8 + 2 * tig;
                float x0 = (oc[df][rr * 2] + sv[d0]) * inv;
                float x1 = (oc[df][rr * 2 + 1] + sv[d0 + 1]) * inv;
                __half h0 = __float2half_rn(x0), h1 = __float2half_rn(x1);
                __half2 ph = __halves2half2(h0, h1);
                __half2 pl = __floats2half2_rn(x0 - __half2float(h0), x1 - __half2float(h1));
                *(uint32_t*)(oH + d0) = *(uint32_t*)&ph;
                *(uint32_t*)(oL + d0) = *(uint32_t*)&pl;
            }
        }
    }
}

// ---------------- launch ----------------
extern "C" void kernel_launch(void* const* d_in, const int* in_sizes, int n_in,
                              void* d_out, int out_size) {
    const float* q  = (const float*)d_in[0];
    const float* k  = (const float*)d_in[1];
    const float* v  = (const float*)d_in[2];
    const int* qm   = (const int*)d_in[3];
    const int* km   = (const int*)d_in[4];
    const int* vm   = (const int*)d_in[5];
    const float* W[4]  = {(const float*)d_in[6], (const float*)d_in[8], (const float*)d_in[10], (const float*)d_in[12]};
    const float* bi[4] = {(const float*)d_in[7], (const float*)d_in[9], (const float*)d_in[11], (const float*)d_in[13]};
    const float* lng[3] = {(const float*)d_in[14], (const float*)d_in[16], (const float*)d_in[18]};
    const float* lnb[3] = {(const float*)d_in[15], (const float*)d_in[17], (const float*)d_in[19]};
    float* out = (float*)d_out;

    const int PROJ_SMEM = 3 * PSTG + 1024;     // 111616
    const int ATTN_SMEM = AKMS + 2 * 512;      // 81920
    cudaFuncSetAttribute(qkv_kernel, cudaFuncAttributeMaxDynamicSharedMemorySize, PROJ_SMEM);
    cudaFuncSetAttribute(outproj_kernel, cudaFuncAttributeMaxDynamicSharedMemorySize, PROJ_SMEM);
    cudaFuncSetAttribute(attn_wmma, cudaFuncAttributeMaxDynamicSharedMemorySize, ATTN_SMEM);

    prep_w4<<<dim3(EM, 4), 128>>>(W[0], W[1], W[2], W[3]);
    prep_x3<<<dim3(TT / 32, EM / 32, 3 * BB), dim3(32, 8)>>>(q, k, v, qm, km, vm);
    init_aux<<<BB, 256>>>(km);

    qkv_kernel<<<dim3(TT / 64, EM / 128, 3 * BB), 256, PROJ_SMEM>>>(
        bi[0], bi[1], bi[2], lng[0], lng[1], lng[2], lnb[0], lnb[1], lnb[2], km);

    attn_wmma<<<dim3(TT / 64, BB * NH), 256, ATTN_SMEM>>>(qm, km);

    outproj_kernel<<<dim3(TT / 64, EM / 128, BB), 256, PROJ_SMEM>>>(bi[3], out);
}

// round 17
// speedup vs baseline: 2.0377x; 1.0468x over previous
#include <cuda_runtime.h>
#include <cuda_fp16.h>
#include <cstdint>

#define BB 2
#define EM 512
#define NH 8
#define DH 64
#define TT 2048
#define EPS 1e-5f

// ---------------- scratch ----------------
__device__ __align__(256) __half g_WH[4][EM * EM];
__device__ __align__(256) __half g_XH[3][BB * TT * EM];
__device__ __align__(256) __half g_XL[BB * TT * EM];        // only V input needs split
__device__ __align__(256) __half g_Qb[BB * NH * TT * DH];
__device__ __align__(256) __half g_Kb[BB * NH * TT * DH];
__device__ __align__(256) __half g_Vb[BB * NH * DH * TT];
__device__ __align__(256) __half g_AoH[BB * TT * EM];
__device__ float g_Sv[BB * NH * DH];
__device__ float g_nv[BB];

// ---------------- helpers ----------------
__device__ __forceinline__ uint32_t smem_u32(const void* p) {
    uint32_t a;
    asm("{ .reg .u64 t; cvta.to.shared.u64 t, %1; cvt.u32.u64 %0, t; }" : "=r"(a) : "l"(p));
    return a;
}
__device__ __forceinline__ void cpa16(uint32_t s, const void* g) {
    asm volatile("cp.async.cg.shared.global [%0], [%1], 16;" :: "r"(s), "l"(g));
}
__device__ __forceinline__ void cpa4(uint32_t s, const void* g) {
    asm volatile("cp.async.ca.shared.global [%0], [%1], 4;" :: "r"(s), "l"(g));
}
#define CP_COMMIT() asm volatile("cp.async.commit_group;" ::: "memory")
#define CP_WAIT1()  asm volatile("cp.async.wait_group 1;" ::: "memory")

__device__ __forceinline__ void ldm_x4(uint32_t* r, uint32_t a) {
    asm volatile("ldmatrix.sync.aligned.m8n8.x4.shared.b16 {%0,%1,%2,%3}, [%4];"
                 : "=r"(r[0]), "=r"(r[1]), "=r"(r[2]), "=r"(r[3]) : "r"(a));
}

__device__ __forceinline__ void mma16816(float* c, const uint32_t* a, const uint32_t* b) {
    asm volatile(
        "mma.sync.aligned.m16n8k16.row.col.f32.f16.f16.f32 "
        "{%0,%1,%2,%3}, {%4,%5,%6,%7}, {%8,%9}, {%0,%1,%2,%3};"
        : "+f"(c[0]), "+f"(c[1]), "+f"(c[2]), "+f"(c[3])
        : "r"(a[0]), "r"(a[1]), "r"(a[2]), "r"(a[3]), "r"(b[0]), "r"(b[1]));
}

__device__ __forceinline__ uint32_t sA_addr(uint32_t base, int stride, int mo, int ko, int lane) {
    int j = lane >> 3, r = lane & 7;
    return base + (uint32_t)((mo + ((j & 1) << 3) + r) * stride + (ko + ((j >> 1) << 3)) * 2);
}
__device__ __forceinline__ uint32_t sB_addr(uint32_t base, int stride, int no, int ko, int lane) {
    int j = lane >> 3, r = lane & 7;
    return base + (uint32_t)((no + ((j >> 1) << 3) + r) * stride + (ko + ((j & 1) << 3)) * 2);
}

__device__ __forceinline__ float expm1p(float s) {
    float p = 1.f / 720.f;
    p = fmaf(p, s, 1.f / 120.f);
    p = fmaf(p, s, 1.f / 24.f);
    p = fmaf(p, s, 1.f / 6.f);
    p = fmaf(p, s, 0.5f);
    p = fmaf(p, s, 1.f);
    return p * s;
}

// ---------------- prep kernels ----------------
__global__ void __launch_bounds__(128) prep_w4(const float* __restrict__ W0,
                                               const float* __restrict__ W1,
                                               const float* __restrict__ W2,
                                               const float* __restrict__ W3) {
    __shared__ float red[8];
    const float* Ws[4] = {W0, W1, W2, W3};
    int i = blockIdx.y, row = blockIdx.x, tid = threadIdx.x;
    const float* wr = Ws[i] + (size_t)row * EM;
    __half* WH = g_WH[i];
    float s = 0.f, s2 = 0.f;
    for (int c = tid; c < EM; c += 128) { float v = wr[c]; s += v; s2 += v * v; }
    for (int o = 16; o; o >>= 1) { s += __shfl_xor_sync(~0u, s, o); s2 += __shfl_xor_sync(~0u, s2, o); }
    if ((tid & 31) == 0) { red[tid >> 5] = s; red[4 + (tid >> 5)] = s2; }
    __syncthreads();
    s = red[0] + red[1] + red[2] + red[3];
    s2 = red[4] + red[5] + red[6] + red[7];
    float mu = s * (1.f / EM), var = s2 * (1.f / EM) - mu * mu, r = rsqrtf(var + EPS);
    for (int c = tid; c < EM; c += 128)
        WH[(size_t)row * EM + c] = __float2half_rn((wr[c] - mu) * r);
}

__global__ void prep_x3(const float* __restrict__ x0, const float* __restrict__ x1,
                        const float* __restrict__ x2,
                        const int* __restrict__ m0, const int* __restrict__ m1,
                        const int* __restrict__ m2) {
    __shared__ float s[32][33];
    const float* Xs[3] = {x0, x1, x2};
    const int* Ms[3] = {m0, m1, m2};
    int which = blockIdx.z >> 1, b = blockIdx.z & 1;
    const float* X = Xs[which];
    const int* mask = Ms[which];
    __half* XH = g_XH[which];
    int t0 = blockIdx.x * 32, i0 = blockIdx.y * 32;
    int tx = threadIdx.x, ty = threadIdx.y;
#pragma unroll
    for (int rr = 0; rr < 4; rr++)
        s[ty + 8 * rr][tx] = X[((size_t)b * EM + i0 + ty + 8 * rr) * TT + t0 + tx];
    __syncthreads();
#pragma unroll
    for (int rr = 0; rr < 4; rr++) {
        int tl = ty + 8 * rr, t = t0 + tl;
        float x = s[tx][tl] * (float)mask[b * TT + t];
        __half h = __float2half_rn(x);
        size_t o = ((size_t)b * TT + t) * EM + i0 + tx;
        XH[o] = h;
        if (which == 2) g_XL[o] = __float2half_rn(x - __half2float(h));
    }
}

__global__ void init_aux(const int* __restrict__ km) {
    __shared__ float red[8];
    int b = blockIdx.x, tid = threadIdx.x;
    for (int i = tid; i < NH * DH; i += 256) g_Sv[b * NH * DH + i] = 0.f;
    float c = 0.f;
    for (int t = tid; t < TT; t += 256) c += (float)km[b * TT + t];
    for (int o = 16; o; o >>= 1) c += __shfl_xor_sync(~0u, c, o);
    if ((tid & 31) == 0) red[tid >> 5] = c;
    __syncthreads();
    if (tid == 0) {
        float tt = 0.f;
        for (int w = 0; w < 8; w++) tt += red[w];
        g_nv[b] = tt;
    }
}

// ---------------- projection core (fp16, K-chunk 64, 3-stage ring, optional split-B) ----------------
// block tile 128m x 64t, ONE sync per 64-k chunk, 2 CTAs/SM.
// Stage (stride 144B): A[128]@0 (18432), Bh[64]@18432 (9216), Bl@27648 (9216); 36864 x 3.
#define PSTR 144
#define PSTG 36864
#define PSY_F 65
__device__ __forceinline__ void proj_core(
    const __half* __restrict__ gA0, const __half* __restrict__ gBh0,
    const __half* __restrict__ gBl0, const float* __restrict__ bias,
    const float* __restrict__ lng, const float* __restrict__ lnb,
    __half* __restrict__ oTD, __half* __restrict__ oDT,
    float* __restrict__ Yout, const int* __restrict__ km,
    int mode, int split, int t0, int m0, int b, char* smc)
{
    uint32_t sb = smem_u32(smc);
    int tid = threadIdx.x, lane = tid & 31, wid = tid >> 5;
    int g = lane >> 2, tig = lane & 3;
    int wm = wid >> 1, wn = wid & 1;
    const __half* gA  = gA0 + (size_t)m0 * EM;
    const __half* gBh = gBh0 + ((size_t)b * TT + t0) * EM;
    const __half* gBl = gBl0 + ((size_t)b * TT + t0) * EM;

    auto issue = [&](int kc, int st) {
        int k0 = kc * 64;
        uint32_t base = sb + st * PSTG;
#pragma unroll
        for (int i = 0; i < 4; i++) {
            int idx = tid + i * 256;
            int r = idx >> 3, j = idx & 7;
            cpa16(base + (uint32_t)(r * PSTR + j * 16), gA + (size_t)r * EM + k0 + j * 8);
        }
#pragma unroll
        for (int i = 0; i < 2; i++) {
            int idx = tid + i * 256;
            int r = idx >> 3, j = idx & 7;
            uint32_t off = (uint32_t)(r * PSTR + j * 16);
            cpa16(base + 18432 + off, gBh + (size_t)r * EM + k0 + j * 8);
            if (split) cpa16(base + 27648 + off, gBl + (size_t)r * EM + k0 + j * 8);
        }
    };

    issue(0, 0); CP_COMMIT();
    issue(1, 1); CP_COMMIT();

    float acc[2][4][4] = {};

    for (int kc = 0; kc < 8; kc++) {
        int st = kc % 3;
        CP_WAIT1();
        __syncthreads();
        uint32_t bA = sb + st * PSTG, bBh = bA + 18432, bBl = bA + 27648;
#pragma unroll
        for (int ks = 0; ks < 4; ks++) {
            uint32_t ah[2][4], bh[2][4], bl[2][4];
#pragma unroll
            for (int mf = 0; mf < 2; mf++)
                ldm_x4(ah[mf], sA_addr(bA, PSTR, wm * 32 + mf * 16, ks * 16, lane));
#pragma unroll
            for (int np = 0; np < 2; np++) {
                ldm_x4(bh[np], sB_addr(bBh, PSTR, wn * 32 + np * 16, ks * 16, lane));
                if (split) ldm_x4(bl[np], sB_addr(bBl, PSTR, wn * 32 + np * 16, ks * 16, lane));
            }
#pragma unroll
            for (int mf = 0; mf < 2; mf++)
#pragma unroll
                for (int nf = 0; nf < 4; nf++) {
                    mma16816(acc[mf][nf], ah[mf], &bh[nf >> 1][(nf & 1) * 2]);
                    if (split) mma16816(acc[mf][nf], ah[mf], &bl[nf >> 1][(nf & 1) * 2]);
                }
        }
        if (kc + 2 < 8) issue(kc + 2, (kc + 2) % 3);
        CP_COMMIT();
    }

    if (mode == 2) {
#pragma unroll
        for (int mf = 0; mf < 2; mf++)
#pragma unroll
            for (int rr = 0; rr < 2; rr++) {
                int m = m0 + wm * 32 + mf * 16 + g + rr * 8;
                float bi = bias[m];
                float* yo = Yout + ((size_t)b * EM + m) * TT + t0 + wn * 32;
#pragma unroll
                for (int nf = 0; nf < 4; nf++) {
                    float2 v = make_float2(acc[mf][nf][rr * 2] + bi, acc[mf][nf][rr * 2 + 1] + bi);
                    *(float2*)(yo + nf * 8 + 2 * tig) = v;
                }
            }
        return;
    }

    // ---- fused LN epilogue ----
    float* sY = (float*)smc;                       // [128][65] fp32
    float* sSvW = (float*)(smc + 128 * PSY_F * 4); // [4][64]
    __syncthreads();
#pragma unroll
    for (int mf = 0; mf < 2; mf++)
#pragma unroll
        for (int rr = 0; rr < 2; rr++) {
            int m = wm * 32 + mf * 16 + g + rr * 8;
            float bi = bias[m0 + m];
#pragma unroll
            for (int nf = 0; nf < 4; nf++) {
                int t = wn * 32 + nf * 8 + 2 * tig;
                sY[m * PSY_F + t] = acc[mf][nf][rr * 2] + bi;
                sY[m * PSY_F + t + 1] = acc[mf][nf][rr * 2 + 1] + bi;
            }
        }
    __syncthreads();

    if (tid < 128) {
        int hh = tid >> 6, tl = tid & 63;
        int t = t0 + tl;
        int h = (m0 >> 6) + hh;
        float v[64];
        float s = 0.f, s2 = 0.f;
#pragma unroll
        for (int d = 0; d < 64; d++) {
            v[d] = sY[(hh * 64 + d) * PSY_F + tl];
            s += v[d]; s2 += v[d] * v[d];
        }
        float mu = s * (1.f / 64), var = s2 * (1.f / 64) - mu * mu, rs = rsqrtf(var + EPS);
#pragma unroll
        for (int d = 0; d < 64; d++) v[d] = (v[d] - mu) * rs * lng[d] + lnb[d];

        if (mode == 0) {
            __half* o = oTD + (((size_t)b * NH + h) * TT + t) * 64;
#pragma unroll
            for (int dd = 0; dd < 64; dd += 8) {
                uint32_t pk[4];
#pragma unroll
                for (int e = 0; e < 4; e++) {
                    __half2 p = __floats2half2_rn(v[dd + 2 * e], v[dd + 2 * e + 1]);
                    pk[e] = *(uint32_t*)&p;
                }
                *(uint4*)(o + dd) = *(uint4*)pk;
            }
        } else {
            __half* o = oDT + ((size_t)b * NH + h) * (size_t)(64 * TT) + t;
#pragma unroll
            for (int d = 0; d < 64; d++) o[(size_t)d * TT] = __float2half_rn(v[d]);
            float w = (float)km[b * TT + t];
#pragma unroll
            for (int d = 0; d < 64; d++) {
                float x = v[d] * w;
                for (int off = 16; off; off >>= 1) x += __shfl_xor_sync(~0u, x, off);
                if (lane == 0) sSvW[wid * 64 + d] = x;
            }
        }
    }
    if (mode == 1) {
        __syncthreads();
        if (tid < 128) {
            int hh = tid >> 6, d = tid & 63;
            float val = sSvW[(hh * 2) * 64 + d] + sSvW[(hh * 2 + 1) * 64 + d];
            atomicAdd(&g_Sv[((size_t)b * NH + (m0 >> 6) + hh) * 64 + d], val);
        }
    }
}

// merged QKV projection: grid (TT/64, EM/128, 3*BB)
__global__ void __launch_bounds__(256, 2) qkv_kernel(
    const float* b0, const float* b1, const float* b2,
    const float* g0, const float* g1, const float* g2,
    const float* e0, const float* e1, const float* e2,
    const int* km)
{
    extern __shared__ __align__(16) char smc[];
    int which = blockIdx.z / BB, b = blockIdx.z % BB;
    const float* biases[3] = {b0, b1, b2};
    const float* lngs[3] = {g0, g1, g2};
    const float* lnbs[3] = {e0, e1, e2};
    __half* oTD = (which == 0) ? g_Qb : g_Kb;
    // Q/K: single-B (error crushed by /181). V: split-B.
    proj_core(g_WH[which], g_XH[which], g_XL,
              biases[which], lngs[which], lnbs[which],
              oTD, g_Vb, nullptr, km,
              (which == 2) ? 1 : 0, (which == 2) ? 1 : 0,
              blockIdx.x * 64, blockIdx.y * 128, b, smc);
}

__global__ void __launch_bounds__(256, 2) outproj_kernel(const float* bias, float* out)
{
    extern __shared__ __align__(16) char smc[];
    proj_core(g_WH[3], g_AoH, g_AoH, bias, nullptr, nullptr,
              nullptr, nullptr, out, nullptr, 2, 0,
              blockIdx.x * 64, blockIdx.y * 128, blockIdx.z, smc);
}

// ---------------- fused attention (split-k, 8 warps, cp.async 2-stage) ----------------
#define ASTG 35840
#define AQSZ 9216
#define AKMS 80896
__global__ void __launch_bounds__(256, 2) attn_wmma(const int* __restrict__ qmask,
                                                    const int* __restrict__ kmask)
{
    extern __shared__ __align__(16) char smc[];
    uint32_t sb = smem_u32(smc);
    __half* sQ = (__half*)smc;
    uint32_t aQ = sb;
    int tid = threadIdx.x, lane = tid & 31, wid = tid >> 5;
    int g = lane >> 2, tig = lane & 3;
    int qs = wid >> 1, kh = wid & 1;
    int q0 = blockIdx.x * 64;
    int b = blockIdx.y >> 3, h = blockIdx.y & 7;
    size_t hb = (size_t)(b * NH + h);
    const __half* gQ = g_Qb + (hb * TT + q0) * 64;
    const __half* gK = g_Kb + hb * TT * 64;
    const __half* gV = g_Vb + hb * (size_t)(64 * TT);

    auto issue = [&](int kc, int st) {
        int k0 = kc * 128;
        uint32_t base = sb + AQSZ + st * ASTG;
#pragma unroll
        for (int i = 0; i < 4; i++) {
            int idx = tid + i * 256;
            int r = idx >> 3, j = idx & 7;
            cpa16(base + (uint32_t)(r * 72 + j * 8) * 2, gK + (size_t)(k0 + r) * 64 + j * 8);
        }
#pragma unroll
        for (int i = 0; i < 4; i++) {
            int idx = tid + i * 256;
            int r = idx >> 4, j = idx & 15;
            cpa16(base + 18432 + (uint32_t)(r * 136 + j * 8) * 2, gV + (size_t)r * TT + k0 + j * 8);
        }
        if (tid < 128) cpa4(sb + AKMS + st * 512 + tid * 4, kmask + b * TT + k0 + tid);
    };

    for (int idx = tid; idx < 512; idx += 256) {
        int r = idx >> 3, j = idx & 7;
        *(uint4*)(sQ + r * 72 + j * 8) = *(const uint4*)(gQ + (size_t)r * 64 + j * 8);
    }

    issue(0, 0); CP_COMMIT();
    issue(1, 1); CP_COMMIT();

    float oc[8][4] = {};
    float rs0 = 0.f, rs1 = 0.f;
    const float inv181 = 1.f / 181.f;

    for (int kc = 0; kc < 16; kc++) {
        int st = kc & 1;
        CP_WAIT1();
        __syncthreads();
        uint32_t aK = sb + AQSZ + st * ASTG, aV = aK + 18432;
        const int* kmsi = (const int*)(smc + AKMS + st * 512);

        float sc[8][4] = {};
#pragma unroll
        for (int ks = 0; ks < 4; ks++) {
            uint32_t aq[4];
            ldm_x4(aq, sA_addr(aQ, 144, qs * 16, ks * 16, lane));
#pragma unroll
            for (int nb = 0; nb < 4; nb++) {
                uint32_t bk[4];
                ldm_x4(bk, sB_addr(aK, 144, kh * 64 + nb * 16, ks * 16, lane));
                mma16816(sc[2 * nb], aq, &bk[0]);
                mma16816(sc[2 * nb + 1], aq, &bk[2]);
            }
        }

        uint32_t ua[4][4];
#pragma unroll
        for (int nf = 0; nf < 8; nf++) {
            int c0 = kh * 64 + nf * 8 + 2 * tig;
            float k0f = (float)kmsi[c0], k1f = (float)kmsi[c0 + 1];
            float u0 = expm1p(sc[nf][0] * inv181) * k0f;
            float u1 = expm1p(sc[nf][1] * inv181) * k1f;
            float u2 = expm1p(sc[nf][2] * inv181) * k0f;
            float u3 = expm1p(sc[nf][3] * inv181) * k1f;
            rs0 += u0 + u1;
            rs1 += u2 + u3;
            __half2 p01 = __floats2half2_rn(u0, u1);
            __half2 p23 = __floats2half2_rn(u2, u3);
            int kk = nf >> 1, hi = (nf & 1) * 2;
            ua[kk][hi] = *(uint32_t*)&p01;
            ua[kk][hi + 1] = *(uint32_t*)&p23;
        }

#pragma unroll
        for (int kk = 0; kk < 4; kk++) {
#pragma unroll
            for (int db = 0; db < 4; db++) {
                uint32_t bv[4];
                ldm_x4(bv, sB_addr(aV, 272, db * 16, kh * 64 + kk * 16, lane));
                mma16816(oc[2 * db], ua[kk], &bv[0]);
                mma16816(oc[2 * db + 1], ua[kk], &bv[2]);
            }
        }
        __syncthreads();
        if (kc + 2 < 16) issue(kc + 2, st);
        CP_COMMIT();
    }

    rs0 += __shfl_xor_sync(~0u, rs0, 1);
    rs0 += __shfl_xor_sync(~0u, rs0, 2);
    rs1 += __shfl_xor_sync(~0u, rs1, 1);
    rs1 += __shfl_xor_sync(~0u, rs1, 2);

    float* red = (float*)(smc + AQSZ);
    if (kh == 1) {
        float* r = &red[(qs * 32 + lane) * 34];
#pragma unroll
        for (int df = 0; df < 8; df++)
#pragma unroll
            for (int e = 0; e < 4; e++) r[df * 4 + e] = oc[df][e];
        r[32] = rs0; r[33] = rs1;
    }
    __syncthreads();
    if (kh == 0) {
        float* r = &red[(qs * 32 + lane) * 34];
#pragma unroll
        for (int df = 0; df < 8; df++)
#pragma unroll
            for (int e = 0; e < 4; e++) oc[df][e] += r[df * 4 + e];
        rs0 += r[32]; rs1 += r[33];

        float nv = g_nv[b];
        const float* sv = g_Sv + hb * 64;
#pragma unroll
        for (int rr = 0; rr < 2; rr++) {
            int row = qs * 16 + g + rr * 8;
            int q = q0 + row;
            float l = nv + (rr ? rs1 : rs0);
            float inv = (qmask[b * TT + q] != 0) ? (1.f / l) : 0.f;
            __half* oH = g_AoH + ((size_t)b * TT + q) * EM + h * 64;
#pragma unroll
            for (int df = 0; df < 8; df++) {
                int d0 = df * 8 + 2 * tig;
                float x0 = (oc[df][rr * 2] + sv[d0]) * inv;
                float x1 = (oc[df][rr * 2 + 1] + sv[d0 + 1]) * inv;
                __half2 ph = __floats2half2_rn(x0, x1);
                *(uint32_t*)(oH + d0) = *(uint32_t*)&ph;
            }
        }
    }
}

// ---------------- launch ----------------
extern "C" void kernel_launch(void* const* d_in, const int* in_sizes, int n_in,
                              void* d_out, int out_size) {
    const float* q  = (const float*)d_in[0];
    const float* k  = (const float*)d_in[1];
    const float* v  = (const float*)d_in[2];
    const int* qm   = (const int*)d_in[3];
    const int* km   = (const int*)d_in[4];
    const int* vm   = (const int*)d_in[5];
    const float* W[4]  = {(const float*)d_in[6], (const float*)d_in[8], (const float*)d_in[10], (const float*)d_in[12]};
    const float* bi[4] = {(const float*)d_in[7], (const float*)d_in[9], (const float*)d_in[11], (const float*)d_in[13]};
    const float* lng[3] = {(const float*)d_in[14], (const float*)d_in[16], (const float*)d_in[18]};
    const float* lnb[3] = {(const float*)d_in[15], (const float*)d_in[17], (const float*)d_in[19]};
    float* out = (float*)d_out;

    const int PROJ_SMEM = 3 * PSTG + 1024;     // 111616
    const int ATTN_SMEM = AKMS + 2 * 512;      // 81920
    cudaFuncSetAttribute(qkv_kernel, cudaFuncAttributeMaxDynamicSharedMemorySize, PROJ_SMEM);
    cudaFuncSetAttribute(outproj_kernel, cudaFuncAttributeMaxDynamicSharedMemorySize, PROJ_SMEM);
    cudaFuncSetAttribute(attn_wmma, cudaFuncAttributeMaxDynamicSharedMemorySize, ATTN_SMEM);

    prep_w4<<<dim3(EM, 4), 128>>>(W[0], W[1], W[2], W[3]);
    prep_x3<<<dim3(TT / 32, EM / 32, 3 * BB), dim3(32, 8)>>>(q, k, v, qm, km, vm);
    init_aux<<<BB, 256>>>(km);

    qkv_kernel<<<dim3(TT / 64, EM / 128, 3 * BB), 256, PROJ_SMEM>>>(
        bi[0], bi[1], bi[2], lng[0], lng[1], lng[2], lnb[0], lnb[1], lnb[2], km);

    attn_wmma<<<dim3(TT / 64, BB * NH), 256, ATTN_SMEM>>>(qm, km);

    outproj_kernel<<<dim3(TT / 64, EM / 128, BB), 256, PROJ_SMEM>>>(bi[3], out);
}